// round 7
// baseline (speedup 1.0000x reference)
#include <cuda_runtime.h>
#include <cstdint>

#define D_MODEL 1024
#define N_HEADS 16
#define D_HEAD  64
#define D_FF    4096
#define BATCH   4
#define SEQ     1024
#define M_TOK   (BATCH*SEQ)   // 4096

// ---------------- scratch (allocation-free: device globals) ----------------
__device__ float g_h   [M_TOK*D_MODEL];
__device__ float g_q   [M_TOK*D_MODEL];
__device__ float g_k   [M_TOK*D_MODEL];
__device__ float g_v   [M_TOK*D_MODEL];
__device__ float g_vT  [M_TOK*D_MODEL];
__device__ float g_o1  [M_TOK*D_MODEL];
__device__ float g_h2  [M_TOK*D_MODEL];
__device__ float g_ff  [M_TOK*D_FF];
__device__ float g_wqkv[3*D_MODEL*D_MODEL];
__device__ float g_w1r [D_FF*D_MODEL];
__device__ float g_w2r [D_MODEL*D_FF];
__device__ float g_stm [64*8*1024];      // per-(z, col-tile, row) max
__device__ float g_stl [64*8*1024];      // per-(z, col-tile, row) sumexp
__device__ float g_rst [64*1024*2];      // per-(z, row): (m, 1/l)

// ---------------- helpers ----------------
__device__ __forceinline__ uint32_t f2tf(float f) {
    uint32_t u;
    asm("cvt.rna.tf32.f32 %0, %1;" : "=r"(u) : "f"(f));
    return u;
}
__device__ __forceinline__ float f2tf_f(float f) { return __uint_as_float(f2tf(f)); }

__device__ __forceinline__ void mma_tf32(float* c, uint32_t a0, uint32_t a1, uint32_t a2, uint32_t a3,
                                         uint32_t b0, uint32_t b1) {
    asm volatile(
        "mma.sync.aligned.m16n8k8.row.col.f32.tf32.tf32.f32 "
        "{%0,%1,%2,%3}, {%4,%5,%6,%7}, {%8,%9}, {%0,%1,%2,%3};\n"
        : "+f"(c[0]), "+f"(c[1]), "+f"(c[2]), "+f"(c[3])
        : "r"(a0), "r"(a1), "r"(a2), "r"(a3), "r"(b0), "r"(b1));
}

// ---------------- round-to-tf32 copy ----------------
__global__ void round_copy(const float4* __restrict__ src, float4* __restrict__ dst, int n4) {
    int i = blockIdx.x * blockDim.x + threadIdx.x;
    if (i < n4) {
        float4 v = src[i];
        dst[i] = make_float4(f2tf_f(v.x), f2tf_f(v.y), f2tf_f(v.z), f2tf_f(v.w));
    }
}

// ---------------- LayerNorm (unbiased var, /(std+eps)); optional tf32-rounded out ----
__global__ void ln_kernel(const float* __restrict__ x, const float* __restrict__ g,
                          const float* __restrict__ b, float* __restrict__ out, int rnd) {
    int row = blockIdx.x;
    int t = threadIdx.x;  // 256 threads, 4 floats each
    const float4* xr = (const float4*)(x + (size_t)row * D_MODEL);
    float4 v = xr[t];
    __shared__ float red[8];

    float s = v.x + v.y + v.z + v.w;
    #pragma unroll
    for (int o = 16; o; o >>= 1) s += __shfl_xor_sync(0xffffffffu, s, o);
    if ((t & 31) == 0) red[t >> 5] = s;
    __syncthreads();
    float tot = red[0]+red[1]+red[2]+red[3]+red[4]+red[5]+red[6]+red[7];
    float mean = tot * (1.0f / D_MODEL);

    float dx = v.x - mean, dy = v.y - mean, dz = v.z - mean, dw = v.w - mean;
    float ss = dx*dx + dy*dy + dz*dz + dw*dw;
    #pragma unroll
    for (int o = 16; o; o >>= 1) ss += __shfl_xor_sync(0xffffffffu, ss, o);
    __syncthreads();
    if ((t & 31) == 0) red[t >> 5] = ss;
    __syncthreads();
    float vtot = red[0]+red[1]+red[2]+red[3]+red[4]+red[5]+red[6]+red[7];
    float inv = 1.0f / (sqrtf(vtot * (1.0f / (D_MODEL - 1))) + 1e-12f);

    float4 g4 = ((const float4*)g)[t];
    float4 b4 = ((const float4*)b)[t];
    float4 o4;
    o4.x = g4.x * dx * inv + b4.x;
    o4.y = g4.y * dy * inv + b4.y;
    o4.z = g4.z * dz * inv + b4.z;
    o4.w = g4.w * dw * inv + b4.w;
    if (rnd) o4 = make_float4(f2tf_f(o4.x), f2tf_f(o4.y), f2tf_f(o4.z), f2tf_f(o4.w));
    ((float4*)(out + (size_t)row * D_MODEL))[t] = o4;
}

// ---------------- V transpose: v[b,s,h,d] -> vT[(b*H+h)*64+d][s] (v pre-rounded) ----
__global__ void transpose_v(const float* __restrict__ v, float* __restrict__ vT) {
    __shared__ float tile[32][33];
    int bh = blockIdx.z;             // b*H + h
    int b = bh / N_HEADS, h = bh % N_HEADS;
    int s0 = blockIdx.x * 32;
    int d0 = blockIdx.y * 32;
    int tx = threadIdx.x, ty = threadIdx.y;  // 32 x 8
    const float* src = v + ((size_t)b * SEQ) * D_MODEL + h * D_HEAD;
    #pragma unroll
    for (int i = 0; i < 32; i += 8)
        tile[ty + i][tx] = src[(size_t)(s0 + ty + i) * D_MODEL + d0 + tx];
    __syncthreads();
    float* dst = vT + ((size_t)bh * D_HEAD) * SEQ;
    #pragma unroll
    for (int i = 0; i < 32; i += 8)
        dst[(size_t)(d0 + ty + i) * SEQ + s0 + tx] = tile[tx][ty + i];
}

// ---------------- per-row softmax stat combine: (m_t, l_t) x8 -> (m, 1/l) ----------
__global__ void stat_combine(const float* __restrict__ stm, const float* __restrict__ stl,
                             float2* __restrict__ rst) {
    int i = blockIdx.x * blockDim.x + threadIdx.x;   // z*1024 + row, 65536 total
    int z = i >> 10, row = i & 1023;
    const float* pm = stm + (size_t)z * 8 * 1024 + row;
    const float* pl = stl + (size_t)z * 8 * 1024 + row;
    float mv[8];
    float m = -1e30f;
    #pragma unroll
    for (int t = 0; t < 8; t++) { mv[t] = pm[t * 1024]; m = fmaxf(m, mv[t]); }
    float l = 0.f;
    #pragma unroll
    for (int t = 0; t < 8; t++) l += pl[t * 1024] * expf(mv[t] - m);
    rst[i] = make_float2(m, 1.0f / l);
}

// ---------------- tf32 mma.sync GEMM, chunk-permuted smem, LDS.128 fragments -------
// C = scale*(A[M,K] @ B[N,K]^T) (+bias)(+res)(relu)(round)
// 128x128 CTA tile, 8 warps in 4x2 grid, 32x64 warp tile, BK=16.
// CVTA: 0 = A already tf32 (raw), 1 = cvt A in staging,
//       2 = softmax-P mode: A holds scores S; transform p=exp(s-m)*linv using rstat,
//           write unrounded p back over A in gmem (each element touched once:
//           requires gridDim.x == 1), feed tf32-rounded p to the MMAs.
// STATS: scores mode — after writing C, reduce per-row max / sumexp of this
//        128-col tile and write to stm/stl at ((z*8+bx)*1024 + m0 + row).
// If Ck != null: QKV mode, output cols [0,1024)->C, [1024,2048)->Ck, [2048,3072)->Cv.
template<int CVTA, int ROUND_OUT, int STATS>
__global__ void __launch_bounds__(256, 2)
gemm_mma(const float* __restrict__ A, const float* __restrict__ B,
         float* __restrict__ C, const float* __restrict__ bias, const float* __restrict__ res,
         float* __restrict__ Ck, float* __restrict__ Cv,
         const float* __restrict__ biask, const float* __restrict__ biasv,
         const float2* __restrict__ rstat, float* __restrict__ stm, float* __restrict__ stl,
         int M, int N, int K, int lda, int ldb, int ldc,
         float scale, int relu, int zmod,
         long long aLo, long long aHi, long long bLo, long long bHi,
         long long cLo, long long cHi)
{
    __shared__ __align__(16) uint32_t sm[8192];   // 2 bufs x (A 2048 + B 2048) words

    int z = blockIdx.z;
    int zlo = z % zmod, zhi = z / zmod;
    A += (size_t)zlo * aLo + (size_t)zhi * aHi;
    B += (size_t)zlo * bLo + (size_t)zhi * bHi;
    size_t coff = (size_t)zlo * cLo + (size_t)zhi * cHi;
    C += coff;
    if (res) res += coff;

    const int tid = threadIdx.x, lane = tid & 31, warp = tid >> 5;
    const int wm = (warp & 3) * 32, wn = (warp >> 2) * 64;
    const int m0 = blockIdx.y * 128, n0 = blockIdx.x * 128;

    // staging-side addressing
    const int lr = tid >> 2, c4 = tid & 3, sw = (lr >> 1) & 3;
    uint32_t stA[4];
    #pragma unroll
    for (int j = 0; j < 4; j++) stA[j] = lr * 16 + 4 * (j ^ sw) + c4;  // buf0 A region
    // compute-side bases
    const int ft = lane & 3, frl = lane >> 2;
    const int fu = ft ^ ((frl >> 1) & 3);
    uint32_t ldA = (uint32_t)((wm + frl) * 16 + 4 * fu);
    uint32_t ldB = (uint32_t)(2048 + (wn + frl) * 16 + 4 * fu);

    // softmax-P mode: per-thread row stats (rows lr and lr+64, fixed)
    float2 st0 = make_float2(0.f, 0.f), st1 = make_float2(0.f, 0.f);
    float* PW = nullptr;
    if (CVTA == 2) {
        st0 = rstat[(size_t)z * 1024 + m0 + lr];
        st1 = rstat[(size_t)z * 1024 + m0 + lr + 64];
        PW = (float*)A;
    }

    float acc[2][8][4];
    #pragma unroll
    for (int i = 0; i < 2; i++)
        #pragma unroll
        for (int j = 0; j < 8; j++)
            #pragma unroll
            for (int c = 0; c < 4; c++) acc[i][j][c] = 0.f;

    float4 aR[2], bR[2];

    auto loadg = [&](int t) {
        int k0 = t * 16 + c4 * 4;
        #pragma unroll
        for (int i = 0; i < 2; i++) {
            int gm = m0 + lr + i * 64;
            aR[i] = (gm < M) ? *(const float4*)(A + (size_t)gm * lda + k0)
                             : make_float4(0.f, 0.f, 0.f, 0.f);
            if (CVTA == 2) {
                float2 s = i ? st1 : st0;
                aR[i].x = expf(aR[i].x - s.x) * s.y;
                aR[i].y = expf(aR[i].y - s.x) * s.y;
                aR[i].z = expf(aR[i].z - s.x) * s.y;
                aR[i].w = expf(aR[i].w - s.x) * s.y;
                if (gm < M) *(float4*)(PW + (size_t)gm * lda + k0) = aR[i];
            }
            int gn = n0 + lr + i * 64;
            bR[i] = (gn < N) ? *(const float4*)(B + (size_t)gn * ldb + k0)
                             : make_float4(0.f, 0.f, 0.f, 0.f);
        }
    };
    auto stores = [&]() {
        #pragma unroll
        for (int i = 0; i < 2; i++) {
            float av[4] = {aR[i].x, aR[i].y, aR[i].z, aR[i].w};
            float bv[4] = {bR[i].x, bR[i].y, bR[i].z, bR[i].w};
            #pragma unroll
            for (int j = 0; j < 4; j++) {
                sm[stA[j] + i * 1024]        = (CVTA != 0) ? f2tf(av[j]) : __float_as_uint(av[j]);
                sm[stA[j] + i * 1024 + 2048] = __float_as_uint(bv[j]);
            }
        }
        #pragma unroll
        for (int j = 0; j < 4; j++) stA[j] ^= 4096;
    };
    auto compute = [&]() {
        uint4 af[2][2];
        #pragma unroll
        for (int mt = 0; mt < 2; mt++)
            #pragma unroll
            for (int h = 0; h < 2; h++)
                af[mt][h] = *(const uint4*)&sm[ldA + mt * 256 + h * 128];
        #pragma unroll
        for (int nt = 0; nt < 8; nt++) {
            uint4 bf = *(const uint4*)&sm[ldB + nt * 128];
            #pragma unroll
            for (int mt = 0; mt < 2; mt++) {
                mma_tf32(acc[mt][nt], af[mt][0].x, af[mt][1].x, af[mt][0].y, af[mt][1].y,
                         bf.x, bf.y);
                mma_tf32(acc[mt][nt], af[mt][0].z, af[mt][1].z, af[mt][0].w, af[mt][1].w,
                         bf.z, bf.w);
            }
        }
        ldA ^= 4096; ldB ^= 4096;
    };

    int nk = K / 16;
    loadg(0); stores(); __syncthreads();
    for (int t = 0; t < nk; ++t) {
        if (t + 1 < nk) loadg(t + 1);
        compute();
        if (t + 1 < nk) stores();
        __syncthreads();
    }

    // epilogue (QKV 3-way select, float2-vectorized)
    float* Cp = C; const float* bp = bias; int noff = 0;
    if (Ck) {
        if (n0 >= 2048)      { Cp = Cv; bp = biasv; noff = 2048; }
        else if (n0 >= 1024) { Cp = Ck; bp = biask; noff = 1024; }
    }
    #pragma unroll
    for (int mt = 0; mt < 2; ++mt) {
        #pragma unroll
        for (int nt = 0; nt < 8; ++nt) {
            int rbase = m0 + wm + mt * 16 + (lane >> 2);
            int cbase = n0 + wn + nt * 8 + (lane & 3) * 2;
            #pragma unroll
            for (int h = 0; h < 2; ++h) {
                int rr = rbase + h * 8;
                int cl = cbase - noff;
                if (rr < M && cbase + 1 < N) {
                    float v0 = acc[mt][nt][h * 2 + 0] * scale;
                    float v1 = acc[mt][nt][h * 2 + 1] * scale;
                    if (bp)  { float2 bb = *(const float2*)(bp + cl); v0 += bb.x; v1 += bb.y; }
                    if (res) { float2 r2 = *(const float2*)(res + (size_t)rr * ldc + cl); v0 += r2.x; v1 += r2.y; }
                    if (relu) { v0 = fmaxf(v0, 0.f); v1 = fmaxf(v1, 0.f); }
                    if (ROUND_OUT) { v0 = f2tf_f(v0); v1 = f2tf_f(v1); }
                    *(float2*)(Cp + (size_t)rr * ldc + cl) = make_float2(v0, v1);
                } else if (rr < M) {
                    #pragma unroll
                    for (int c = 0; c < 2; ++c) {
                        int cc = cbase + c;
                        if (cc < N) {
                            float val = acc[mt][nt][h * 2 + c] * scale;
                            if (bp)  val += bp[cc - noff];
                            if (res) val += res[(size_t)rr * ldc + cc - noff];
                            if (relu) val = fmaxf(val, 0.f);
                            if (ROUND_OUT) val = f2tf_f(val);
                            Cp[(size_t)rr * ldc + cc - noff] = val;
                        }
                    }
                }
            }
        }
    }

    // ---- softmax stats epilogue (scores mode) ----
    if (STATS) {
        float* smf = (float*)sm;
        const int g = warp >> 2;           // wn group (0/1)
        const int rl = lane >> 2;
        // local row maxes over this warp's 16 cols per row (scaled)
        float lmax[2][2];
        #pragma unroll
        for (int mt = 0; mt < 2; mt++)
            #pragma unroll
            for (int h = 0; h < 2; h++) {
                float v = -1e30f;
                #pragma unroll
                for (int nt = 0; nt < 8; nt++) {
                    v = fmaxf(v, acc[mt][nt][2 * h]);
                    v = fmaxf(v, acc[mt][nt][2 * h + 1]);
                }
                lmax[mt][h] = v * scale;
            }
        #pragma unroll
        for (int o = 1; o < 4; o <<= 1)
            #pragma unroll
            for (int mt = 0; mt < 2; mt++)
                #pragma unroll
                for (int h = 0; h < 2; h++)
                    lmax[mt][h] = fmaxf(lmax[mt][h], __shfl_xor_sync(0xffffffffu, lmax[mt][h], o));
        __syncthreads();                   // sm[] free for reuse
        if ((lane & 3) == 0)
            #pragma unroll
            for (int mt = 0; mt < 2; mt++)
                #pragma unroll
                for (int h = 0; h < 2; h++)
                    smf[g * 128 + wm + mt * 16 + h * 8 + rl] = lmax[mt][h];
        __syncthreads();
        float rmax[2][2], lsum[2][2];
        #pragma unroll
        for (int mt = 0; mt < 2; mt++)
            #pragma unroll
            for (int h = 0; h < 2; h++) {
                int row = wm + mt * 16 + h * 8 + rl;
                float m = fmaxf(smf[row], smf[128 + row]);
                rmax[mt][h] = m;
                float s = 0.f;
                #pragma unroll
                for (int nt = 0; nt < 8; nt++) {
                    s += expf(acc[mt][nt][2 * h] * scale - m);
                    s += expf(acc[mt][nt][2 * h + 1] * scale - m);
                }
                lsum[mt][h] = s;
            }
        #pragma unroll
        for (int o = 1; o < 4; o <<= 1)
            #pragma unroll
            for (int mt = 0; mt < 2; mt++)
                #pragma unroll
                for (int h = 0; h < 2; h++)
                    lsum[mt][h] += __shfl_xor_sync(0xffffffffu, lsum[mt][h], o);
        __syncthreads();
        if ((lane & 3) == 0)
            #pragma unroll
            for (int mt = 0; mt < 2; mt++)
                #pragma unroll
                for (int h = 0; h < 2; h++)
                    smf[256 + g * 128 + wm + mt * 16 + h * 8 + rl] = lsum[mt][h];
        __syncthreads();
        if (g == 0 && (lane & 3) == 0) {
            #pragma unroll
            for (int mt = 0; mt < 2; mt++)
                #pragma unroll
                for (int h = 0; h < 2; h++) {
                    int row = wm + mt * 16 + h * 8 + rl;
                    size_t idx = ((size_t)z * 8 + blockIdx.x) * 1024 + m0 + row;
                    stm[idx] = rmax[mt][h];
                    stl[idx] = smf[256 + row] + smf[384 + row];
                }
        }
    }
}

// ---------------- launch ----------------
extern "C" void kernel_launch(void* const* d_in, const int* in_sizes, int n_in,
                              void* d_out, int out_size) {
    const float* x     = (const float*)d_in[0];
    const float* ln1_g = (const float*)d_in[1];
    const float* ln1_b = (const float*)d_in[2];
    const float* wq    = (const float*)d_in[3];
    const float* bq    = (const float*)d_in[4];
    const float* wk    = (const float*)d_in[5];
    const float* bk    = (const float*)d_in[6];
    const float* wv    = (const float*)d_in[7];
    const float* bv    = (const float*)d_in[8];
    const float* ln2_g = (const float*)d_in[9];
    const float* ln2_b = (const float*)d_in[10];
    const float* w1    = (const float*)d_in[11];
    const float* b1    = (const float*)d_in[12];
    const float* w2    = (const float*)d_in[13];
    const float* b2    = (const float*)d_in[14];

    float* out  = (float*)d_out;
    float* attn = out + (size_t)BATCH * SEQ * D_MODEL;

    float *h, *q, *k, *v, *vT, *o1, *h2, *ff, *wqkv, *w1r, *w2r, *stm, *stl, *rst;
    cudaGetSymbolAddress((void**)&h,    g_h);
    cudaGetSymbolAddress((void**)&q,    g_q);
    cudaGetSymbolAddress((void**)&k,    g_k);
    cudaGetSymbolAddress((void**)&v,    g_v);
    cudaGetSymbolAddress((void**)&vT,   g_vT);
    cudaGetSymbolAddress((void**)&o1,   g_o1);
    cudaGetSymbolAddress((void**)&h2,   g_h2);
    cudaGetSymbolAddress((void**)&ff,   g_ff);
    cudaGetSymbolAddress((void**)&wqkv, g_wqkv);
    cudaGetSymbolAddress((void**)&w1r,  g_w1r);
    cudaGetSymbolAddress((void**)&w2r,  g_w2r);
    cudaGetSymbolAddress((void**)&stm,  g_stm);
    cudaGetSymbolAddress((void**)&stl,  g_stl);
    cudaGetSymbolAddress((void**)&rst,  g_rst);

    dim3 blk(256);
    const int N4_1M = D_MODEL * D_MODEL / 4;      // 262144
    const int N4_4M = D_FF * D_MODEL / 4;         // 1048576

    // 0) pre-round weights into scratch
    round_copy<<<(N4_1M + 255) / 256, 256>>>((const float4*)wq, (float4*)(wqkv), N4_1M);
    round_copy<<<(N4_1M + 255) / 256, 256>>>((const float4*)wk, (float4*)(wqkv + D_MODEL * D_MODEL), N4_1M);
    round_copy<<<(N4_1M + 255) / 256, 256>>>((const float4*)wv, (float4*)(wqkv + 2 * D_MODEL * D_MODEL), N4_1M);
    round_copy<<<(N4_4M + 255) / 256, 256>>>((const float4*)w1, (float4*)w1r, N4_4M);
    round_copy<<<(N4_4M + 255) / 256, 256>>>((const float4*)w2, (float4*)w2r, N4_4M);

    // 1) LN1 (rounded output)
    ln_kernel<<<M_TOK, 256>>>(x, ln1_g, ln1_b, h, 1);

    // 2) fused QKV: [4096,3072] = h @ wqkv^T, outputs split to q/k/v, rounded
    gemm_mma<0, 1, 0><<<dim3(24, 32, 1), blk>>>(h, wqkv, q, bq, nullptr, k, v, bk, bv,
        nullptr, nullptr, nullptr,
        M_TOK, 3 * D_MODEL, D_MODEL, D_MODEL, D_MODEL, D_MODEL, 1.f, 0, 1, 0,0,0,0,0,0);

    // 3) V transpose (v already rounded)
    transpose_v<<<dim3(32, 2, BATCH * N_HEADS), dim3(32, 8)>>>(v, vT);

    // 4) scores = q @ k^T / 8, straight into attn region, + per-tile softmax stats
    gemm_mma<0, 0, 1><<<dim3(8, 8, N_HEADS * BATCH), blk>>>(q, k, attn, nullptr, nullptr,
        nullptr, nullptr, nullptr, nullptr,
        nullptr, stm, stl,
        SEQ, SEQ, D_HEAD, D_MODEL, D_MODEL, SEQ, 0.125f, 0, BATCH,
        (long long)SEQ * D_MODEL, 64,
        (long long)SEQ * D_MODEL, 64,
        (long long)SEQ * SEQ, (long long)BATCH * SEQ * SEQ);

    // 5) combine per-tile stats -> per-row (m, 1/l)
    stat_combine<<<256, 256>>>(stm, stl, (float2*)rst);

    // 6) ctx = P @ vT^T (+ residual x); A-path converts S->P in-flight and
    //    writes the normalized probabilities back into the attn output region.
    gemm_mma<2, 0, 0><<<dim3(1, 8, N_HEADS * BATCH), blk>>>(attn, vT, o1, nullptr, x,
        nullptr, nullptr, nullptr, nullptr,
        (const float2*)rst, nullptr, nullptr,
        SEQ, D_HEAD, SEQ, SEQ, SEQ, D_MODEL, 1.f, 0, BATCH,
        (long long)SEQ * SEQ, (long long)BATCH * SEQ * SEQ,
        (long long)N_HEADS * D_HEAD * SEQ, (long long)D_HEAD * SEQ,
        (long long)SEQ * D_MODEL, 64);

    // 7) LN2 (rounded output)
    ln_kernel<<<M_TOK, 256>>>(o1, ln2_g, ln2_b, h2, 1);

    // 8) FFN1: relu(h2 @ w1^T + b1), rounded output
    gemm_mma<0, 1, 0><<<dim3(32, 32, 1), blk>>>(h2, w1r, ff, b1, nullptr,
        nullptr, nullptr, nullptr, nullptr,
        nullptr, nullptr, nullptr,
        M_TOK, D_FF, D_MODEL, D_MODEL, D_MODEL, D_FF, 1.f, 1, 1, 0,0,0,0,0,0);

    // 9) FFN2: ff @ w2^T + b2 + o1 -> final out (exact)
    gemm_mma<0, 0, 0><<<dim3(8, 32, 1), blk>>>(ff, w2r, out, b2, o1,
        nullptr, nullptr, nullptr, nullptr,
        nullptr, nullptr, nullptr,
        M_TOK, D_MODEL, D_FF, D_FF, D_FF, D_MODEL, 1.f, 0, 1, 0,0,0,0,0,0);
}

// round 8
// speedup vs baseline: 1.0274x; 1.0274x over previous
#include <cuda_runtime.h>
#include <cstdint>

#define D_MODEL 1024
#define N_HEADS 16
#define D_HEAD  64
#define D_FF    4096
#define BATCH   4
#define SEQ     1024
#define M_TOK   (BATCH*SEQ)   // 4096

// ---------------- scratch (allocation-free: device globals) ----------------
__device__ float g_h   [M_TOK*D_MODEL];
__device__ float g_q   [M_TOK*D_MODEL];
__device__ float g_k   [M_TOK*D_MODEL];
__device__ float g_v   [M_TOK*D_MODEL];
__device__ float g_vT  [M_TOK*D_MODEL];
__device__ float g_o1  [M_TOK*D_MODEL];
__device__ float g_h2  [M_TOK*D_MODEL];
__device__ float g_ff  [M_TOK*D_FF];
__device__ float g_wqkv[3*D_MODEL*D_MODEL];
__device__ float g_w1r [D_FF*D_MODEL];
__device__ float g_w2r [D_MODEL*D_FF];
__device__ float g_stm [64*8*1024];      // per-(z, col-tile, row) max
__device__ float g_stl [64*8*1024];      // per-(z, col-tile, row) sumexp
__device__ float g_scl [64*8*1024];      // per-(z, col-tile, row) exp(m_t-m)/l

// ---------------- helpers ----------------
__device__ __forceinline__ uint32_t f2tf(float f) {
    uint32_t u;
    asm("cvt.rna.tf32.f32 %0, %1;" : "=r"(u) : "f"(f));
    return u;
}
__device__ __forceinline__ float f2tf_f(float f) { return __uint_as_float(f2tf(f)); }

__device__ __forceinline__ void mma_tf32(float* c, uint32_t a0, uint32_t a1, uint32_t a2, uint32_t a3,
                                         uint32_t b0, uint32_t b1) {
    asm volatile(
        "mma.sync.aligned.m16n8k8.row.col.f32.tf32.tf32.f32 "
        "{%0,%1,%2,%3}, {%4,%5,%6,%7}, {%8,%9}, {%0,%1,%2,%3};\n"
        : "+f"(c[0]), "+f"(c[1]), "+f"(c[2]), "+f"(c[3])
        : "r"(a0), "r"(a1), "r"(a2), "r"(a3), "r"(b0), "r"(b1));
}

// ---------------- round-to-tf32 copy ----------------
__global__ void round_copy(const float4* __restrict__ src, float4* __restrict__ dst, int n4) {
    int i = blockIdx.x * blockDim.x + threadIdx.x;
    if (i < n4) {
        float4 v = src[i];
        dst[i] = make_float4(f2tf_f(v.x), f2tf_f(v.y), f2tf_f(v.z), f2tf_f(v.w));
    }
}

// ---------------- LayerNorm (unbiased var, /(std+eps)); optional tf32-rounded out ----
__global__ void ln_kernel(const float* __restrict__ x, const float* __restrict__ g,
                          const float* __restrict__ b, float* __restrict__ out, int rnd) {
    int row = blockIdx.x;
    int t = threadIdx.x;  // 256 threads, 4 floats each
    const float4* xr = (const float4*)(x + (size_t)row * D_MODEL);
    float4 v = xr[t];
    __shared__ float red[8];

    float s = v.x + v.y + v.z + v.w;
    #pragma unroll
    for (int o = 16; o; o >>= 1) s += __shfl_xor_sync(0xffffffffu, s, o);
    if ((t & 31) == 0) red[t >> 5] = s;
    __syncthreads();
    float tot = red[0]+red[1]+red[2]+red[3]+red[4]+red[5]+red[6]+red[7];
    float mean = tot * (1.0f / D_MODEL);

    float dx = v.x - mean, dy = v.y - mean, dz = v.z - mean, dw = v.w - mean;
    float ss = dx*dx + dy*dy + dz*dz + dw*dw;
    #pragma unroll
    for (int o = 16; o; o >>= 1) ss += __shfl_xor_sync(0xffffffffu, ss, o);
    __syncthreads();
    if ((t & 31) == 0) red[t >> 5] = ss;
    __syncthreads();
    float vtot = red[0]+red[1]+red[2]+red[3]+red[4]+red[5]+red[6]+red[7];
    float inv = 1.0f / (sqrtf(vtot * (1.0f / (D_MODEL - 1))) + 1e-12f);

    float4 g4 = ((const float4*)g)[t];
    float4 b4 = ((const float4*)b)[t];
    float4 o4;
    o4.x = g4.x * dx * inv + b4.x;
    o4.y = g4.y * dy * inv + b4.y;
    o4.z = g4.z * dz * inv + b4.z;
    o4.w = g4.w * dw * inv + b4.w;
    if (rnd) o4 = make_float4(f2tf_f(o4.x), f2tf_f(o4.y), f2tf_f(o4.z), f2tf_f(o4.w));
    ((float4*)(out + (size_t)row * D_MODEL))[t] = o4;
}

// ---------------- V transpose: v[b,s,h,d] -> vT[(b*H+h)*64+d][s] (v pre-rounded) ----
__global__ void transpose_v(const float* __restrict__ v, float* __restrict__ vT) {
    __shared__ float tile[32][33];
    int bh = blockIdx.z;             // b*H + h
    int b = bh / N_HEADS, h = bh % N_HEADS;
    int s0 = blockIdx.x * 32;
    int d0 = blockIdx.y * 32;
    int tx = threadIdx.x, ty = threadIdx.y;  // 32 x 8
    const float* src = v + ((size_t)b * SEQ) * D_MODEL + h * D_HEAD;
    #pragma unroll
    for (int i = 0; i < 32; i += 8)
        tile[ty + i][tx] = src[(size_t)(s0 + ty + i) * D_MODEL + d0 + tx];
    __syncthreads();
    float* dst = vT + ((size_t)bh * D_HEAD) * SEQ;
    #pragma unroll
    for (int i = 0; i < 32; i += 8)
        dst[(size_t)(d0 + ty + i) * SEQ + s0 + tx] = tile[tx][ty + i];
}

// ---------------- stat combine: (m_t, l_t) x8 -> per-tile scale exp(m_t-m)/l ------
__global__ void stat_combine(const float* __restrict__ stm, const float* __restrict__ stl,
                             float* __restrict__ scl) {
    int i = blockIdx.x * blockDim.x + threadIdx.x;   // z*1024 + row, 65536 total
    int z = i >> 10, row = i & 1023;
    const float* pm = stm + (size_t)z * 8 * 1024 + row;
    const float* pl = stl + (size_t)z * 8 * 1024 + row;
    float mv[8];
    float m = -1e30f;
    #pragma unroll
    for (int t = 0; t < 8; t++) { mv[t] = pm[t * 1024]; m = fmaxf(m, mv[t]); }
    float ex[8];
    float l = 0.f;
    #pragma unroll
    for (int t = 0; t < 8; t++) { ex[t] = expf(mv[t] - m); l += pl[t * 1024] * ex[t]; }
    float inv = 1.0f / l;
    float* ps = scl + (size_t)z * 8 * 1024 + row;
    #pragma unroll
    for (int t = 0; t < 8; t++) ps[t * 1024] = ex[t] * inv;
}

// ---------------- tf32 mma.sync GEMM, chunk-permuted smem, LDS.128 fragments -------
// C = scale*(A[M,K] @ B[N,K]^T) (+bias)(+res)(relu)(round)
// 128x128 CTA tile, 8 warps in 4x2 grid, 32x64 warp tile, BK=16.
// CVTA: 0 = A already tf32 (raw), 1 = cvt A in staging,
//       2 = attn-P mode: A holds E = exp(s - m_tile); p = E * scl[z][ktile][row];
//           write p back over A in gmem (each element touched once: gridDim.x==1),
//           feed tf32-rounded p to the MMAs.
// STATS: scores mode — compute per-row tile max m_t, write C = exp(s - m_t)
//        (instead of s), and store (m_t, sumexp) to stm/stl.
// If Ck != null: QKV mode, output cols [0,1024)->C, [1024,2048)->Ck, [2048,3072)->Cv.
template<int CVTA, int ROUND_OUT, int STATS>
__global__ void __launch_bounds__(256, 2)
gemm_mma(const float* __restrict__ A, const float* __restrict__ B,
         float* __restrict__ C, const float* __restrict__ bias, const float* __restrict__ res,
         float* __restrict__ Ck, float* __restrict__ Cv,
         const float* __restrict__ biask, const float* __restrict__ biasv,
         const float* __restrict__ scl, float* __restrict__ stm, float* __restrict__ stl,
         int M, int N, int K, int lda, int ldb, int ldc,
         float scale, int relu, int zmod,
         long long aLo, long long aHi, long long bLo, long long bHi,
         long long cLo, long long cHi)
{
    __shared__ __align__(16) uint32_t sm[8192];   // 2 bufs x (A 2048 + B 2048) words

    int z = blockIdx.z;
    int zlo = z % zmod, zhi = z / zmod;
    A += (size_t)zlo * aLo + (size_t)zhi * aHi;
    B += (size_t)zlo * bLo + (size_t)zhi * bHi;
    size_t coff = (size_t)zlo * cLo + (size_t)zhi * cHi;
    C += coff;
    if (res) res += coff;

    const int tid = threadIdx.x, lane = tid & 31, warp = tid >> 5;
    const int wm = (warp & 3) * 32, wn = (warp >> 2) * 64;
    const int m0 = blockIdx.y * 128, n0 = blockIdx.x * 128;

    // staging-side addressing
    const int lr = tid >> 2, c4 = tid & 3, sw = (lr >> 1) & 3;
    uint32_t stA[4];
    #pragma unroll
    for (int j = 0; j < 4; j++) stA[j] = lr * 16 + 4 * (j ^ sw) + c4;  // buf0 A region
    // compute-side bases
    const int ft = lane & 3, frl = lane >> 2;
    const int fu = ft ^ ((frl >> 1) & 3);
    uint32_t ldA = (uint32_t)((wm + frl) * 16 + 4 * fu);
    uint32_t ldB = (uint32_t)(2048 + (wn + frl) * 16 + 4 * fu);

    float* PW = (CVTA == 2) ? (float*)A : nullptr;

    float acc[2][8][4];
    #pragma unroll
    for (int i = 0; i < 2; i++)
        #pragma unroll
        for (int j = 0; j < 8; j++)
            #pragma unroll
            for (int c = 0; c < 4; c++) acc[i][j][c] = 0.f;

    float4 aR[2], bR[2];

    auto loadg = [&](int t) {
        int k0 = t * 16 + c4 * 4;
        float s0 = 0.f, s1 = 0.f;
        if (CVTA == 2) {
            const float* sp = scl + ((size_t)z * 8 + (t >> 3)) * 1024 + m0 + lr;
            s0 = sp[0]; s1 = sp[64];
        }
        #pragma unroll
        for (int i = 0; i < 2; i++) {
            int gm = m0 + lr + i * 64;
            aR[i] = (gm < M) ? *(const float4*)(A + (size_t)gm * lda + k0)
                             : make_float4(0.f, 0.f, 0.f, 0.f);
            if (CVTA == 2) {
                float s = i ? s1 : s0;
                aR[i].x *= s; aR[i].y *= s; aR[i].z *= s; aR[i].w *= s;
                if (gm < M) *(float4*)(PW + (size_t)gm * lda + k0) = aR[i];
            }
            int gn = n0 + lr + i * 64;
            bR[i] = (gn < N) ? *(const float4*)(B + (size_t)gn * ldb + k0)
                             : make_float4(0.f, 0.f, 0.f, 0.f);
        }
    };
    auto stores = [&]() {
        #pragma unroll
        for (int i = 0; i < 2; i++) {
            float av[4] = {aR[i].x, aR[i].y, aR[i].z, aR[i].w};
            float bv[4] = {bR[i].x, bR[i].y, bR[i].z, bR[i].w};
            #pragma unroll
            for (int j = 0; j < 4; j++) {
                sm[stA[j] + i * 1024]        = (CVTA != 0) ? f2tf(av[j]) : __float_as_uint(av[j]);
                sm[stA[j] + i * 1024 + 2048] = __float_as_uint(bv[j]);
            }
        }
        #pragma unroll
        for (int j = 0; j < 4; j++) stA[j] ^= 4096;
    };
    auto compute = [&]() {
        uint4 af[2][2];
        #pragma unroll
        for (int mt = 0; mt < 2; mt++)
            #pragma unroll
            for (int h = 0; h < 2; h++)
                af[mt][h] = *(const uint4*)&sm[ldA + mt * 256 + h * 128];
        #pragma unroll
        for (int nt = 0; nt < 8; nt++) {
            uint4 bf = *(const uint4*)&sm[ldB + nt * 128];
            #pragma unroll
            for (int mt = 0; mt < 2; mt++) {
                mma_tf32(acc[mt][nt], af[mt][0].x, af[mt][1].x, af[mt][0].y, af[mt][1].y,
                         bf.x, bf.y);
                mma_tf32(acc[mt][nt], af[mt][0].z, af[mt][1].z, af[mt][0].w, af[mt][1].w,
                         bf.z, bf.w);
            }
        }
        ldA ^= 4096; ldB ^= 4096;
    };

    int nk = K / 16;
    loadg(0); stores(); __syncthreads();
    for (int t = 0; t < nk; ++t) {
        if (t + 1 < nk) loadg(t + 1);
        compute();
        if (t + 1 < nk) stores();
        __syncthreads();
    }

    if (STATS) {
        // ---- scores mode: per-row tile max, write E = exp(s - m_t), store stats ----
        float* smf = (float*)sm;
        const int g = warp >> 2;           // wn group (0/1)
        const int rl = lane >> 2;
        float lmax[2][2];
        #pragma unroll
        for (int mt = 0; mt < 2; mt++)
            #pragma unroll
            for (int h = 0; h < 2; h++) {
                float v = -1e30f;
                #pragma unroll
                for (int nt = 0; nt < 8; nt++) {
                    v = fmaxf(v, acc[mt][nt][2 * h]);
                    v = fmaxf(v, acc[mt][nt][2 * h + 1]);
                }
                lmax[mt][h] = v * scale;
            }
        #pragma unroll
        for (int o = 1; o < 4; o <<= 1)
            #pragma unroll
            for (int mt = 0; mt < 2; mt++)
                #pragma unroll
                for (int h = 0; h < 2; h++)
                    lmax[mt][h] = fmaxf(lmax[mt][h], __shfl_xor_sync(0xffffffffu, lmax[mt][h], o));
        __syncthreads();                   // sm[] free for reuse
        if ((lane & 3) == 0)
            #pragma unroll
            for (int mt = 0; mt < 2; mt++)
                #pragma unroll
                for (int h = 0; h < 2; h++)
                    smf[g * 128 + wm + mt * 16 + h * 8 + rl] = lmax[mt][h];
        __syncthreads();
        float rmax[2][2], lsum[2][2];
        #pragma unroll
        for (int mt = 0; mt < 2; mt++)
            #pragma unroll
            for (int h = 0; h < 2; h++) {
                int row = wm + mt * 16 + h * 8 + rl;
                rmax[mt][h] = fmaxf(smf[row], smf[128 + row]);
                lsum[mt][h] = 0.f;
            }
        // write E values + accumulate sums
        #pragma unroll
        for (int mt = 0; mt < 2; ++mt) {
            #pragma unroll
            for (int nt = 0; nt < 8; ++nt) {
                int rbase = m0 + wm + mt * 16 + rl;
                int cbase = n0 + wn + nt * 8 + (lane & 3) * 2;
                #pragma unroll
                for (int h = 0; h < 2; ++h) {
                    float e0 = expf(acc[mt][nt][2 * h]     * scale - rmax[mt][h]);
                    float e1 = expf(acc[mt][nt][2 * h + 1] * scale - rmax[mt][h]);
                    *(float2*)(C + (size_t)(rbase + h * 8) * ldc + cbase) = make_float2(e0, e1);
                    lsum[mt][h] += e0 + e1;
                }
            }
        }
        #pragma unroll
        for (int o = 1; o < 4; o <<= 1)
            #pragma unroll
            for (int mt = 0; mt < 2; mt++)
                #pragma unroll
                for (int h = 0; h < 2; h++)
                    lsum[mt][h] += __shfl_xor_sync(0xffffffffu, lsum[mt][h], o);
        if ((lane & 3) == 0)
            #pragma unroll
            for (int mt = 0; mt < 2; mt++)
                #pragma unroll
                for (int h = 0; h < 2; h++)
                    smf[256 + g * 128 + wm + mt * 16 + h * 8 + rl] = lsum[mt][h];
        __syncthreads();
        if (g == 0 && (lane & 3) == 0) {
            #pragma unroll
            for (int mt = 0; mt < 2; mt++)
                #pragma unroll
                for (int h = 0; h < 2; h++) {
                    int row = wm + mt * 16 + h * 8 + rl;
                    size_t idx = ((size_t)z * 8 + blockIdx.x) * 1024 + m0 + row;
                    stm[idx] = rmax[mt][h];
                    stl[idx] = smf[256 + row] + smf[384 + row];
                }
        }
    } else {
        // ---- normal epilogue (QKV 3-way select, float2-vectorized) ----
        float* Cp = C; const float* bp = bias; int noff = 0;
        if (Ck) {
            if (n0 >= 2048)      { Cp = Cv; bp = biasv; noff = 2048; }
            else if (n0 >= 1024) { Cp = Ck; bp = biask; noff = 1024; }
        }
        #pragma unroll
        for (int mt = 0; mt < 2; ++mt) {
            #pragma unroll
            for (int nt = 0; nt < 8; ++nt) {
                int rbase = m0 + wm + mt * 16 + (lane >> 2);
                int cbase = n0 + wn + nt * 8 + (lane & 3) * 2;
                #pragma unroll
                for (int h = 0; h < 2; ++h) {
                    int rr = rbase + h * 8;
                    int cl = cbase - noff;
                    if (rr < M && cbase + 1 < N) {
                        float v0 = acc[mt][nt][h * 2 + 0] * scale;
                        float v1 = acc[mt][nt][h * 2 + 1] * scale;
                        if (bp)  { float2 bb = *(const float2*)(bp + cl); v0 += bb.x; v1 += bb.y; }
                        if (res) { float2 r2 = *(const float2*)(res + (size_t)rr * ldc + cl); v0 += r2.x; v1 += r2.y; }
                        if (relu) { v0 = fmaxf(v0, 0.f); v1 = fmaxf(v1, 0.f); }
                        if (ROUND_OUT) { v0 = f2tf_f(v0); v1 = f2tf_f(v1); }
                        *(float2*)(Cp + (size_t)rr * ldc + cl) = make_float2(v0, v1);
                    } else if (rr < M) {
                        #pragma unroll
                        for (int c = 0; c < 2; ++c) {
                            int cc = cbase + c;
                            if (cc < N) {
                                float val = acc[mt][nt][h * 2 + c] * scale;
                                if (bp)  val += bp[cc - noff];
                                if (res) val += res[(size_t)rr * ldc + cc - noff];
                                if (relu) val = fmaxf(val, 0.f);
                                if (ROUND_OUT) val = f2tf_f(val);
                                Cp[(size_t)rr * ldc + cc - noff] = val;
                            }
                        }
                    }
                }
            }
        }
    }
}

// ---------------- launch ----------------
extern "C" void kernel_launch(void* const* d_in, const int* in_sizes, int n_in,
                              void* d_out, int out_size) {
    const float* x     = (const float*)d_in[0];
    const float* ln1_g = (const float*)d_in[1];
    const float* ln1_b = (const float*)d_in[2];
    const float* wq    = (const float*)d_in[3];
    const float* bq    = (const float*)d_in[4];
    const float* wk    = (const float*)d_in[5];
    const float* bk    = (const float*)d_in[6];
    const float* wv    = (const float*)d_in[7];
    const float* bv    = (const float*)d_in[8];
    const float* ln2_g = (const float*)d_in[9];
    const float* ln2_b = (const float*)d_in[10];
    const float* w1    = (const float*)d_in[11];
    const float* b1    = (const float*)d_in[12];
    const float* w2    = (const float*)d_in[13];
    const float* b2    = (const float*)d_in[14];

    float* out  = (float*)d_out;
    float* attn = out + (size_t)BATCH * SEQ * D_MODEL;

    float *h, *q, *k, *v, *vT, *o1, *h2, *ff, *wqkv, *w1r, *w2r, *stm, *stl, *scl;
    cudaGetSymbolAddress((void**)&h,    g_h);
    cudaGetSymbolAddress((void**)&q,    g_q);
    cudaGetSymbolAddress((void**)&k,    g_k);
    cudaGetSymbolAddress((void**)&v,    g_v);
    cudaGetSymbolAddress((void**)&vT,   g_vT);
    cudaGetSymbolAddress((void**)&o1,   g_o1);
    cudaGetSymbolAddress((void**)&h2,   g_h2);
    cudaGetSymbolAddress((void**)&ff,   g_ff);
    cudaGetSymbolAddress((void**)&wqkv, g_wqkv);
    cudaGetSymbolAddress((void**)&w1r,  g_w1r);
    cudaGetSymbolAddress((void**)&w2r,  g_w2r);
    cudaGetSymbolAddress((void**)&stm,  g_stm);
    cudaGetSymbolAddress((void**)&stl,  g_stl);
    cudaGetSymbolAddress((void**)&scl,  g_scl);

    dim3 blk(256);
    const int N4_1M = D_MODEL * D_MODEL / 4;      // 262144
    const int N4_4M = D_FF * D_MODEL / 4;         // 1048576

    // 0) pre-round weights into scratch
    round_copy<<<(N4_1M + 255) / 256, 256>>>((const float4*)wq, (float4*)(wqkv), N4_1M);
    round_copy<<<(N4_1M + 255) / 256, 256>>>((const float4*)wk, (float4*)(wqkv + D_MODEL * D_MODEL), N4_1M);
    round_copy<<<(N4_1M + 255) / 256, 256>>>((const float4*)wv, (float4*)(wqkv + 2 * D_MODEL * D_MODEL), N4_1M);
    round_copy<<<(N4_4M + 255) / 256, 256>>>((const float4*)w1, (float4*)w1r, N4_4M);
    round_copy<<<(N4_4M + 255) / 256, 256>>>((const float4*)w2, (float4*)w2r, N4_4M);

    // 1) LN1 (rounded output)
    ln_kernel<<<M_TOK, 256>>>(x, ln1_g, ln1_b, h, 1);

    // 2) fused QKV: [4096,3072] = h @ wqkv^T, outputs split to q/k/v, rounded
    gemm_mma<0, 1, 0><<<dim3(24, 32, 1), blk>>>(h, wqkv, q, bq, nullptr, k, v, bk, bv,
        nullptr, nullptr, nullptr,
        M_TOK, 3 * D_MODEL, D_MODEL, D_MODEL, D_MODEL, D_MODEL, 1.f, 0, 1, 0,0,0,0,0,0);

    // 3) V transpose (v already rounded)
    transpose_v<<<dim3(32, 2, BATCH * N_HEADS), dim3(32, 8)>>>(v, vT);

    // 4) scores -> E = exp(s/8 - m_tile) straight into attn region, + tile stats
    gemm_mma<0, 0, 1><<<dim3(8, 8, N_HEADS * BATCH), blk>>>(q, k, attn, nullptr, nullptr,
        nullptr, nullptr, nullptr, nullptr,
        nullptr, stm, stl,
        SEQ, SEQ, D_HEAD, D_MODEL, D_MODEL, SEQ, 0.125f, 0, BATCH,
        (long long)SEQ * D_MODEL, 64,
        (long long)SEQ * D_MODEL, 64,
        (long long)SEQ * SEQ, (long long)BATCH * SEQ * SEQ);

    // 5) combine per-tile stats -> per-(tile,row) scale exp(m_t-m)/l
    stat_combine<<<256, 256>>>(stm, stl, scl);

    // 6) ctx = P @ vT^T (+ residual x); A-path rescales E->P (one FMA per elt)
    //    and writes normalized P back into the attn output region.
    gemm_mma<2, 0, 0><<<dim3(1, 8, N_HEADS * BATCH), blk>>>(attn, vT, o1, nullptr, x,
        nullptr, nullptr, nullptr, nullptr,
        scl, nullptr, nullptr,
        SEQ, D_HEAD, SEQ, SEQ, SEQ, D_MODEL, 1.f, 0, BATCH,
        (long long)SEQ * SEQ, (long long)BATCH * SEQ * SEQ,
        (long long)N_HEADS * D_HEAD * SEQ, (long long)D_HEAD * SEQ,
        (long long)SEQ * D_MODEL, 64);

    // 7) LN2 (rounded output)
    ln_kernel<<<M_TOK, 256>>>(o1, ln2_g, ln2_b, h2, 1);

    // 8) FFN1: relu(h2 @ w1^T + b1), rounded output
    gemm_mma<0, 1, 0><<<dim3(32, 32, 1), blk>>>(h2, w1r, ff, b1, nullptr,
        nullptr, nullptr, nullptr, nullptr,
        nullptr, nullptr, nullptr,
        M_TOK, D_FF, D_MODEL, D_MODEL, D_MODEL, D_FF, 1.f, 1, 1, 0,0,0,0,0,0);

    // 9) FFN2: ff @ w2^T + b2 + o1 -> final out (exact)
    gemm_mma<0, 0, 0><<<dim3(8, 32, 1), blk>>>(ff, w2r, out, b2, o1,
        nullptr, nullptr, nullptr, nullptr,
        nullptr, nullptr, nullptr,
        M_TOK, D_MODEL, D_FF, D_FF, D_FF, D_MODEL, 1.f, 0, 1, 0,0,0,0,0,0);
}

// round 9
// speedup vs baseline: 1.0794x; 1.0506x over previous
#include <cuda_runtime.h>
#include <cstdint>

#define D_MODEL 1024
#define N_HEADS 16
#define D_HEAD  64
#define D_FF    4096
#define BATCH   4
#define SEQ     1024
#define M_TOK   (BATCH*SEQ)   // 4096

// ---------------- scratch (allocation-free: device globals) ----------------
__device__ float g_h   [M_TOK*D_MODEL];
__device__ float g_q   [M_TOK*D_MODEL];
__device__ float g_k   [M_TOK*D_MODEL];
__device__ float g_v   [M_TOK*D_MODEL];
__device__ float g_vT  [M_TOK*D_MODEL];
__device__ float g_o1  [M_TOK*D_MODEL];
__device__ float g_h2  [M_TOK*D_MODEL];
__device__ float g_ff  [M_TOK*D_FF];
__device__ float g_wqkv[3*D_MODEL*D_MODEL];
__device__ float g_w1r [D_FF*D_MODEL];
__device__ float g_w2r [D_MODEL*D_FF];
__device__ float g_stm [64*8*1024];      // per-(z, col-tile, row) max
__device__ float g_stl [64*8*1024];      // per-(z, col-tile, row) sumexp
__device__ float g_scl [64*8*1024];      // per-(z, col-tile, row) exp(m_t-m)/l

// ---------------- helpers ----------------
__device__ __forceinline__ uint32_t f2tf(float f) {
    uint32_t u;
    asm("cvt.rna.tf32.f32 %0, %1;" : "=r"(u) : "f"(f));
    return u;
}
__device__ __forceinline__ float f2tf_f(float f) { return __uint_as_float(f2tf(f)); }

__device__ __forceinline__ void mma_tf32(float* c, uint32_t a0, uint32_t a1, uint32_t a2, uint32_t a3,
                                         uint32_t b0, uint32_t b1) {
    asm volatile(
        "mma.sync.aligned.m16n8k8.row.col.f32.tf32.tf32.f32 "
        "{%0,%1,%2,%3}, {%4,%5,%6,%7}, {%8,%9}, {%0,%1,%2,%3};\n"
        : "+f"(c[0]), "+f"(c[1]), "+f"(c[2]), "+f"(c[3])
        : "r"(a0), "r"(a1), "r"(a2), "r"(a3), "r"(b0), "r"(b1));
}

// ---------------- round-to-tf32 copy ----------------
__global__ void round_copy(const float4* __restrict__ src, float4* __restrict__ dst, int n4) {
    int i = blockIdx.x * blockDim.x + threadIdx.x;
    if (i < n4) {
        float4 v = src[i];
        dst[i] = make_float4(f2tf_f(v.x), f2tf_f(v.y), f2tf_f(v.z), f2tf_f(v.w));
    }
}

// ---------------- LayerNorm (unbiased var, /(std+eps)); optional tf32-rounded out ----
__global__ void ln_kernel(const float* __restrict__ x, const float* __restrict__ g,
                          const float* __restrict__ b, float* __restrict__ out, int rnd) {
    int row = blockIdx.x;
    int t = threadIdx.x;  // 256 threads, 4 floats each
    const float4* xr = (const float4*)(x + (size_t)row * D_MODEL);
    float4 v = xr[t];
    __shared__ float red[8];

    float s = v.x + v.y + v.z + v.w;
    #pragma unroll
    for (int o = 16; o; o >>= 1) s += __shfl_xor_sync(0xffffffffu, s, o);
    if ((t & 31) == 0) red[t >> 5] = s;
    __syncthreads();
    float tot = red[0]+red[1]+red[2]+red[3]+red[4]+red[5]+red[6]+red[7];
    float mean = tot * (1.0f / D_MODEL);

    float dx = v.x - mean, dy = v.y - mean, dz = v.z - mean, dw = v.w - mean;
    float ss = dx*dx + dy*dy + dz*dz + dw*dw;
    #pragma unroll
    for (int o = 16; o; o >>= 1) ss += __shfl_xor_sync(0xffffffffu, ss, o);
    __syncthreads();
    if ((t & 31) == 0) red[t >> 5] = ss;
    __syncthreads();
    float vtot = red[0]+red[1]+red[2]+red[3]+red[4]+red[5]+red[6]+red[7];
    float inv = 1.0f / (sqrtf(vtot * (1.0f / (D_MODEL - 1))) + 1e-12f);

    float4 g4 = ((const float4*)g)[t];
    float4 b4 = ((const float4*)b)[t];
    float4 o4;
    o4.x = g4.x * dx * inv + b4.x;
    o4.y = g4.y * dy * inv + b4.y;
    o4.z = g4.z * dz * inv + b4.z;
    o4.w = g4.w * dw * inv + b4.w;
    if (rnd) o4 = make_float4(f2tf_f(o4.x), f2tf_f(o4.y), f2tf_f(o4.z), f2tf_f(o4.w));
    ((float4*)(out + (size_t)row * D_MODEL))[t] = o4;
}

// ---------------- V transpose: v[b,s,h,d] -> vT[(b*H+h)*64+d][s] (v pre-rounded) ----
__global__ void transpose_v(const float* __restrict__ v, float* __restrict__ vT) {
    __shared__ float tile[32][33];
    int bh = blockIdx.z;             // b*H + h
    int b = bh / N_HEADS, h = bh % N_HEADS;
    int s0 = blockIdx.x * 32;
    int d0 = blockIdx.y * 32;
    int tx = threadIdx.x, ty = threadIdx.y;  // 32 x 8
    const float* src = v + ((size_t)b * SEQ) * D_MODEL + h * D_HEAD;
    #pragma unroll
    for (int i = 0; i < 32; i += 8)
        tile[ty + i][tx] = src[(size_t)(s0 + ty + i) * D_MODEL + d0 + tx];
    __syncthreads();
    float* dst = vT + ((size_t)bh * D_HEAD) * SEQ;
    #pragma unroll
    for (int i = 0; i < 32; i += 8)
        dst[(size_t)(d0 + ty + i) * SEQ + s0 + tx] = tile[tx][ty + i];
}

// ---------------- stat combine: (m_t, l_t) x8 -> per-tile scale exp(m_t-m)/l ------
__global__ void stat_combine(const float* __restrict__ stm, const float* __restrict__ stl,
                             float* __restrict__ scl) {
    int i = blockIdx.x * blockDim.x + threadIdx.x;   // z*1024 + row, 65536 total
    int z = i >> 10, row = i & 1023;
    const float* pm = stm + (size_t)z * 8 * 1024 + row;
    const float* pl = stl + (size_t)z * 8 * 1024 + row;
    float mv[8];
    float m = -1e30f;
    #pragma unroll
    for (int t = 0; t < 8; t++) { mv[t] = pm[t * 1024]; m = fmaxf(m, mv[t]); }
    float ex[8];
    float l = 0.f;
    #pragma unroll
    for (int t = 0; t < 8; t++) { ex[t] = __expf(mv[t] - m); l += pl[t * 1024] * ex[t]; }
    float inv = 1.0f / l;
    float* ps = scl + (size_t)z * 8 * 1024 + row;
    #pragma unroll
    for (int t = 0; t < 8; t++) ps[t * 1024] = ex[t] * inv;
}

// ---------------- tf32 mma.sync GEMM, chunk-permuted smem, LDS.128 fragments -------
// C = scale*(A[M,K] @ B[N,K]^T) (+bias)(+res)(relu)(round)
// 128 x (16*NT) CTA tile, 8 warps in 4x2 grid, warp tile 32 x (NT*8), BK=16.
// CVTA: 0 = A already tf32 (raw), 1 = cvt A in staging,
//       2 = attn-P mode: A holds E = exp(s - m_tile); p = E * scl[z][ktile][row];
//           write p back over A in gmem (each element touched once: gridDim.x==1),
//           feed tf32-rounded p to the MMAs.
// STATS (requires NT=8): scores mode — per-row tile max m_t, write C = exp(s-m_t),
//        store (m_t, sumexp) to stm/stl.
// If Ck != null: QKV mode, output cols [0,1024)->C, [1024,2048)->Ck, [2048,3072)->Cv.
template<int CVTA, int ROUND_OUT, int STATS, int NT>
__global__ void __launch_bounds__(256, 2)
gemm_mma(const float* __restrict__ A, const float* __restrict__ B,
         float* __restrict__ C, const float* __restrict__ bias, const float* __restrict__ res,
         float* __restrict__ Ck, float* __restrict__ Cv,
         const float* __restrict__ biask, const float* __restrict__ biasv,
         const float* __restrict__ scl, float* __restrict__ stm, float* __restrict__ stl,
         int M, int N, int K, int lda, int ldb, int ldc,
         float scale, int relu, int zmod,
         long long aLo, long long aHi, long long bLo, long long bHi,
         long long cLo, long long cHi)
{
    __shared__ __align__(16) uint32_t sm[8192];   // 2 bufs x (A 2048 + B 2048) words

    int z = blockIdx.z;
    int zlo = z % zmod, zhi = z / zmod;
    A += (size_t)zlo * aLo + (size_t)zhi * aHi;
    B += (size_t)zlo * bLo + (size_t)zhi * bHi;
    size_t coff = (size_t)zlo * cLo + (size_t)zhi * cHi;
    C += coff;
    if (res) res += coff;

    const int tid = threadIdx.x, lane = tid & 31, warp = tid >> 5;
    const int wm = (warp & 3) * 32, wn = (warp >> 2) * (NT * 8);
    const int m0 = blockIdx.y * 128, n0 = blockIdx.x * (16 * NT);

    // staging-side addressing
    const int lr = tid >> 2, c4 = tid & 3, sw = (lr >> 1) & 3;
    uint32_t stA[4];
    #pragma unroll
    for (int j = 0; j < 4; j++) stA[j] = lr * 16 + 4 * (j ^ sw) + c4;  // buf0 A region
    // compute-side bases
    const int ft = lane & 3, frl = lane >> 2;
    const int fu = ft ^ ((frl >> 1) & 3);
    uint32_t ldA = (uint32_t)((wm + frl) * 16 + 4 * fu);
    uint32_t ldB = (uint32_t)(2048 + (wn + frl) * 16 + 4 * fu);

    float* PW = (CVTA == 2) ? (float*)A : nullptr;

    float acc[2][NT][4];
    #pragma unroll
    for (int i = 0; i < 2; i++)
        #pragma unroll
        for (int j = 0; j < NT; j++)
            #pragma unroll
            for (int c = 0; c < 4; c++) acc[i][j][c] = 0.f;

    float4 aR[2], bR[NT / 4];

    auto loadg = [&](int t) {
        int k0 = t * 16 + c4 * 4;
        float s0 = 0.f, s1 = 0.f;
        if (CVTA == 2) {
            const float* sp = scl + ((size_t)z * 8 + (t >> 3)) * 1024 + m0 + lr;
            s0 = sp[0]; s1 = sp[64];
        }
        #pragma unroll
        for (int i = 0; i < 2; i++) {
            int gm = m0 + lr + i * 64;
            aR[i] = (gm < M) ? *(const float4*)(A + (size_t)gm * lda + k0)
                             : make_float4(0.f, 0.f, 0.f, 0.f);
            if (CVTA == 2) {
                float s = i ? s1 : s0;
                aR[i].x *= s; aR[i].y *= s; aR[i].z *= s; aR[i].w *= s;
                if (gm < M) *(float4*)(PW + (size_t)gm * lda + k0) = aR[i];
            }
        }
        #pragma unroll
        for (int i = 0; i < NT / 4; i++) {
            int gn = n0 + lr + i * 64;
            bR[i] = (gn < N) ? *(const float4*)(B + (size_t)gn * ldb + k0)
                             : make_float4(0.f, 0.f, 0.f, 0.f);
        }
    };
    auto stores = [&]() {
        #pragma unroll
        for (int i = 0; i < 2; i++) {
            float av[4] = {aR[i].x, aR[i].y, aR[i].z, aR[i].w};
            #pragma unroll
            for (int j = 0; j < 4; j++)
                sm[stA[j] + i * 1024] = (CVTA != 0) ? f2tf(av[j]) : __float_as_uint(av[j]);
        }
        #pragma unroll
        for (int i = 0; i < NT / 4; i++) {
            float bv[4] = {bR[i].x, bR[i].y, bR[i].z, bR[i].w};
            #pragma unroll
            for (int j = 0; j < 4; j++)
                sm[stA[j] + i * 1024 + 2048] = __float_as_uint(bv[j]);
        }
        #pragma unroll
        for (int j = 0; j < 4; j++) stA[j] ^= 4096;
    };
    auto compute = [&]() {
        uint4 af[2][2];
        #pragma unroll
        for (int mt = 0; mt < 2; mt++)
            #pragma unroll
            for (int h = 0; h < 2; h++)
                af[mt][h] = *(const uint4*)&sm[ldA + mt * 256 + h * 128];
        #pragma unroll
        for (int nt = 0; nt < NT; nt++) {
            uint4 bf = *(const uint4*)&sm[ldB + nt * 128];
            #pragma unroll
            for (int mt = 0; mt < 2; mt++) {
                mma_tf32(acc[mt][nt], af[mt][0].x, af[mt][1].x, af[mt][0].y, af[mt][1].y,
                         bf.x, bf.y);
                mma_tf32(acc[mt][nt], af[mt][0].z, af[mt][1].z, af[mt][0].w, af[mt][1].w,
                         bf.z, bf.w);
            }
        }
        ldA ^= 4096; ldB ^= 4096;
    };

    int nk = K / 16;
    loadg(0); stores(); __syncthreads();
    for (int t = 0; t < nk; ++t) {
        if (t + 1 < nk) loadg(t + 1);
        compute();
        if (t + 1 < nk) stores();
        __syncthreads();
    }

    if (STATS) {
        // ---- scores mode: per-row tile max, write E = exp(s - m_t), store stats ----
        float* smf = (float*)sm;
        const int g = warp >> 2;           // wn group (0/1)
        const int rl = lane >> 2;
        float lmax[2][2];
        #pragma unroll
        for (int mt = 0; mt < 2; mt++)
            #pragma unroll
            for (int h = 0; h < 2; h++) {
                float v = -1e30f;
                #pragma unroll
                for (int nt = 0; nt < NT; nt++) {
                    v = fmaxf(v, acc[mt][nt][2 * h]);
                    v = fmaxf(v, acc[mt][nt][2 * h + 1]);
                }
                lmax[mt][h] = v * scale;
            }
        #pragma unroll
        for (int o = 1; o < 4; o <<= 1)
            #pragma unroll
            for (int mt = 0; mt < 2; mt++)
                #pragma unroll
                for (int h = 0; h < 2; h++)
                    lmax[mt][h] = fmaxf(lmax[mt][h], __shfl_xor_sync(0xffffffffu, lmax[mt][h], o));
        __syncthreads();                   // sm[] free for reuse
        if ((lane & 3) == 0)
            #pragma unroll
            for (int mt = 0; mt < 2; mt++)
                #pragma unroll
                for (int h = 0; h < 2; h++)
                    smf[g * 128 + wm + mt * 16 + h * 8 + rl] = lmax[mt][h];
        __syncthreads();
        float rmax[2][2], lsum[2][2];
        #pragma unroll
        for (int mt = 0; mt < 2; mt++)
            #pragma unroll
            for (int h = 0; h < 2; h++) {
                int row = wm + mt * 16 + h * 8 + rl;
                rmax[mt][h] = fmaxf(smf[row], smf[128 + row]);
                lsum[mt][h] = 0.f;
            }
        // write E values + accumulate sums (fast exp: ~1e-6 rel on probs)
        #pragma unroll
        for (int mt = 0; mt < 2; ++mt) {
            #pragma unroll
            for (int nt = 0; nt < NT; ++nt) {
                int rbase = m0 + wm + mt * 16 + rl;
                int cbase = n0 + wn + nt * 8 + (lane & 3) * 2;
                #pragma unroll
                for (int h = 0; h < 2; ++h) {
                    float e0 = __expf(acc[mt][nt][2 * h]     * scale - rmax[mt][h]);
                    float e1 = __expf(acc[mt][nt][2 * h + 1] * scale - rmax[mt][h]);
                    *(float2*)(C + (size_t)(rbase + h * 8) * ldc + cbase) = make_float2(e0, e1);
                    lsum[mt][h] += e0 + e1;
                }
            }
        }
        #pragma unroll
        for (int o = 1; o < 4; o <<= 1)
            #pragma unroll
            for (int mt = 0; mt < 2; mt++)
                #pragma unroll
                for (int h = 0; h < 2; h++)
                    lsum[mt][h] += __shfl_xor_sync(0xffffffffu, lsum[mt][h], o);
        if ((lane & 3) == 0)
            #pragma unroll
            for (int mt = 0; mt < 2; mt++)
                #pragma unroll
                for (int h = 0; h < 2; h++)
                    smf[256 + g * 128 + wm + mt * 16 + h * 8 + rl] = lsum[mt][h];
        __syncthreads();
        if (g == 0 && (lane & 3) == 0) {
            #pragma unroll
            for (int mt = 0; mt < 2; mt++)
                #pragma unroll
                for (int h = 0; h < 2; h++) {
                    int row = wm + mt * 16 + h * 8 + rl;
                    size_t idx = ((size_t)z * 8 + blockIdx.x) * 1024 + m0 + row;
                    stm[idx] = rmax[mt][h];
                    stl[idx] = smf[256 + row] + smf[384 + row];
                }
        }
    } else {
        // ---- normal epilogue (QKV 3-way select, float2-vectorized) ----
        float* Cp = C; const float* bp = bias; int noff = 0;
        if (Ck) {
            if (n0 >= 2048)      { Cp = Cv; bp = biasv; noff = 2048; }
            else if (n0 >= 1024) { Cp = Ck; bp = biask; noff = 1024; }
        }
        #pragma unroll
        for (int mt = 0; mt < 2; ++mt) {
            #pragma unroll
            for (int nt = 0; nt < NT; ++nt) {
                int rbase = m0 + wm + mt * 16 + (lane >> 2);
                int cbase = n0 + wn + nt * 8 + (lane & 3) * 2;
                #pragma unroll
                for (int h = 0; h < 2; ++h) {
                    int rr = rbase + h * 8;
                    int cl = cbase - noff;
                    if (rr < M && cbase + 1 < N) {
                        float v0 = acc[mt][nt][h * 2 + 0] * scale;
                        float v1 = acc[mt][nt][h * 2 + 1] * scale;
                        if (bp)  { float2 bb = *(const float2*)(bp + cl); v0 += bb.x; v1 += bb.y; }
                        if (res) { float2 r2 = *(const float2*)(res + (size_t)rr * ldc + cl); v0 += r2.x; v1 += r2.y; }
                        if (relu) { v0 = fmaxf(v0, 0.f); v1 = fmaxf(v1, 0.f); }
                        if (ROUND_OUT) { v0 = f2tf_f(v0); v1 = f2tf_f(v1); }
                        *(float2*)(Cp + (size_t)rr * ldc + cl) = make_float2(v0, v1);
                    } else if (rr < M) {
                        #pragma unroll
                        for (int c = 0; c < 2; ++c) {
                            int cc = cbase + c;
                            if (cc < N) {
                                float val = acc[mt][nt][h * 2 + c] * scale;
                                if (bp)  val += bp[cc - noff];
                                if (res) val += res[(size_t)rr * ldc + cc - noff];
                                if (relu) val = fmaxf(val, 0.f);
                                if (ROUND_OUT) val = f2tf_f(val);
                                Cp[(size_t)rr * ldc + cc - noff] = val;
                            }
                        }
                    }
                }
            }
        }
    }
}

// ---------------- launch ----------------
extern "C" void kernel_launch(void* const* d_in, const int* in_sizes, int n_in,
                              void* d_out, int out_size) {
    const float* x     = (const float*)d_in[0];
    const float* ln1_g = (const float*)d_in[1];
    const float* ln1_b = (const float*)d_in[2];
    const float* wq    = (const float*)d_in[3];
    const float* bq    = (const float*)d_in[4];
    const float* wk    = (const float*)d_in[5];
    const float* bk    = (const float*)d_in[6];
    const float* wv    = (const float*)d_in[7];
    const float* bv    = (const float*)d_in[8];
    const float* ln2_g = (const float*)d_in[9];
    const float* ln2_b = (const float*)d_in[10];
    const float* w1    = (const float*)d_in[11];
    const float* b1    = (const float*)d_in[12];
    const float* w2    = (const float*)d_in[13];
    const float* b2    = (const float*)d_in[14];

    float* out  = (float*)d_out;
    float* attn = out + (size_t)BATCH * SEQ * D_MODEL;

    float *h, *q, *k, *v, *vT, *o1, *h2, *ff, *wqkv, *w1r, *w2r, *stm, *stl, *scl;
    cudaGetSymbolAddress((void**)&h,    g_h);
    cudaGetSymbolAddress((void**)&q,    g_q);
    cudaGetSymbolAddress((void**)&k,    g_k);
    cudaGetSymbolAddress((void**)&v,    g_v);
    cudaGetSymbolAddress((void**)&vT,   g_vT);
    cudaGetSymbolAddress((void**)&o1,   g_o1);
    cudaGetSymbolAddress((void**)&h2,   g_h2);
    cudaGetSymbolAddress((void**)&ff,   g_ff);
    cudaGetSymbolAddress((void**)&wqkv, g_wqkv);
    cudaGetSymbolAddress((void**)&w1r,  g_w1r);
    cudaGetSymbolAddress((void**)&w2r,  g_w2r);
    cudaGetSymbolAddress((void**)&stm,  g_stm);
    cudaGetSymbolAddress((void**)&stl,  g_stl);
    cudaGetSymbolAddress((void**)&scl,  g_scl);

    dim3 blk(256);
    const int N4_1M = D_MODEL * D_MODEL / 4;      // 262144
    const int N4_4M = D_FF * D_MODEL / 4;         // 1048576

    // 0) pre-round weights into scratch
    round_copy<<<(N4_1M + 255) / 256, 256>>>((const float4*)wq, (float4*)(wqkv), N4_1M);
    round_copy<<<(N4_1M + 255) / 256, 256>>>((const float4*)wk, (float4*)(wqkv + D_MODEL * D_MODEL), N4_1M);
    round_copy<<<(N4_1M + 255) / 256, 256>>>((const float4*)wv, (float4*)(wqkv + 2 * D_MODEL * D_MODEL), N4_1M);
    round_copy<<<(N4_4M + 255) / 256, 256>>>((const float4*)w1, (float4*)w1r, N4_4M);
    round_copy<<<(N4_4M + 255) / 256, 256>>>((const float4*)w2, (float4*)w2r, N4_4M);

    // 1) LN1 (rounded output)
    ln_kernel<<<M_TOK, 256>>>(x, ln1_g, ln1_b, h, 1);

    // 2) fused QKV: [4096,3072] = h @ wqkv^T, outputs split to q/k/v, rounded
    gemm_mma<0, 1, 0, 8><<<dim3(24, 32, 1), blk>>>(h, wqkv, q, bq, nullptr, k, v, bk, bv,
        nullptr, nullptr, nullptr,
        M_TOK, 3 * D_MODEL, D_MODEL, D_MODEL, D_MODEL, D_MODEL, 1.f, 0, 1, 0,0,0,0,0,0);

    // 3) V transpose (v already rounded)
    transpose_v<<<dim3(32, 2, BATCH * N_HEADS), dim3(32, 8)>>>(v, vT);

    // 4) scores -> E = exp(s/8 - m_tile) straight into attn region, + tile stats
    gemm_mma<0, 0, 1, 8><<<dim3(8, 8, N_HEADS * BATCH), blk>>>(q, k, attn, nullptr, nullptr,
        nullptr, nullptr, nullptr, nullptr,
        nullptr, stm, stl,
        SEQ, SEQ, D_HEAD, D_MODEL, D_MODEL, SEQ, 0.125f, 0, BATCH,
        (long long)SEQ * D_MODEL, 64,
        (long long)SEQ * D_MODEL, 64,
        (long long)SEQ * SEQ, (long long)BATCH * SEQ * SEQ);

    // 5) combine per-tile stats -> per-(tile,row) scale exp(m_t-m)/l
    stat_combine<<<256, 256>>>(stm, stl, scl);

    // 6) ctx = P @ vT^T (+ residual x); BN=64 tile (no wasted MMAs), A-path
    //    rescales E->P (one FMA per elt) and writes normalized P back.
    gemm_mma<2, 0, 0, 4><<<dim3(1, 8, N_HEADS * BATCH), blk>>>(attn, vT, o1, nullptr, x,
        nullptr, nullptr, nullptr, nullptr,
        scl, nullptr, nullptr,
        SEQ, D_HEAD, SEQ, SEQ, SEQ, D_MODEL, 1.f, 0, BATCH,
        (long long)SEQ * SEQ, (long long)BATCH * SEQ * SEQ,
        (long long)N_HEADS * D_HEAD * SEQ, (long long)D_HEAD * SEQ,
        (long long)SEQ * D_MODEL, 64);

    // 7) LN2 (rounded output)
    ln_kernel<<<M_TOK, 256>>>(o1, ln2_g, ln2_b, h2, 1);

    // 8) FFN1: relu(h2 @ w1^T + b1), rounded output
    gemm_mma<0, 1, 0, 8><<<dim3(32, 32, 1), blk>>>(h2, w1r, ff, b1, nullptr,
        nullptr, nullptr, nullptr, nullptr,
        nullptr, nullptr, nullptr,
        M_TOK, D_FF, D_MODEL, D_MODEL, D_MODEL, D_FF, 1.f, 1, 1, 0,0,0,0,0,0);

    // 9) FFN2: ff @ w2^T + b2 + o1 -> final out (exact)
    gemm_mma<0, 0, 0, 8><<<dim3(8, 32, 1), blk>>>(ff, w2r, out, b2, o1,
        nullptr, nullptr, nullptr, nullptr,
        nullptr, nullptr, nullptr,
        M_TOK, D_MODEL, D_FF, D_FF, D_FF, D_MODEL, 1.f, 0, 1, 0,0,0,0,0,0);
}

// round 10
// speedup vs baseline: 1.1845x; 1.0973x over previous
#include <cuda_runtime.h>
#include <cstdint>

#define D_MODEL 1024
#define N_HEADS 16
#define D_HEAD  64
#define D_FF    4096
#define BATCH   4
#define SEQ     1024
#define M_TOK   (BATCH*SEQ)   // 4096

// ---------------- scratch (allocation-free: device globals) ----------------
__device__ float g_h   [M_TOK*D_MODEL];
__device__ float g_q   [M_TOK*D_MODEL];
__device__ float g_k   [M_TOK*D_MODEL];
__device__ float g_v   [M_TOK*D_MODEL];
__device__ float g_vT  [M_TOK*D_MODEL];
__device__ float g_o1  [M_TOK*D_MODEL];
__device__ float g_h2  [M_TOK*D_MODEL];
__device__ float g_ff  [M_TOK*D_FF];
__device__ float g_wqkv[3*D_MODEL*D_MODEL];
__device__ float g_w1r [D_FF*D_MODEL];
__device__ float g_w2r [D_MODEL*D_FF];
__device__ float g_stm [64*8*1024];
__device__ float g_stl [64*8*1024];
__device__ float g_scl [64*8*1024];

// ---------------- helpers ----------------
__device__ __forceinline__ uint32_t f2tf(float f) {
    uint32_t u;
    asm("cvt.rna.tf32.f32 %0, %1;" : "=r"(u) : "f"(f));
    return u;
}
__device__ __forceinline__ float f2tf_f(float f) { return __uint_as_float(f2tf(f)); }

// permuted column position: within each 16-block, k -> 4*(k&3) + ((k>>2)&3)
__device__ __forceinline__ int permc(int c) {
    return (c & ~15) | (((c & 3) << 2) | ((c >> 2) & 3));
}

__device__ __forceinline__ uint32_t smem_u32(const void* p) {
    uint32_t a;
    asm("{ .reg .u64 t; cvta.to.shared.u64 t, %1; cvt.u32.u64 %0, t; }" : "=r"(a) : "l"(p));
    return a;
}

__device__ __forceinline__ void cp_async16(uint32_t saddr, const void* gptr) {
    asm volatile("cp.async.cg.shared.global [%0], [%1], 16;" :: "r"(saddr), "l"(gptr) : "memory");
}
__device__ __forceinline__ void cp_commit() {
    asm volatile("cp.async.commit_group;" ::: "memory");
}
__device__ __forceinline__ void cp_wait1() {
    asm volatile("cp.async.wait_group 1;" ::: "memory");
}

__device__ __forceinline__ void mma_tf32(float* c, uint32_t a0, uint32_t a1, uint32_t a2, uint32_t a3,
                                         uint32_t b0, uint32_t b1) {
    asm volatile(
        "mma.sync.aligned.m16n8k8.row.col.f32.tf32.tf32.f32 "
        "{%0,%1,%2,%3}, {%4,%5,%6,%7}, {%8,%9}, {%0,%1,%2,%3};\n"
        : "+f"(c[0]), "+f"(c[1]), "+f"(c[2]), "+f"(c[3])
        : "r"(a0), "r"(a1), "r"(a2), "r"(a3), "r"(b0), "r"(b1));
}

// ---------------- round-to-tf32 copy, PERMUTED output ----------------
__global__ void round_copy(const float4* __restrict__ src, float* __restrict__ dst, int n4) {
    int i = blockIdx.x * blockDim.x + threadIdx.x;
    if (i < n4) {
        float4 v = src[i];
        float* p = dst + 16 * (i >> 2) + (i & 3);
        p[0]  = f2tf_f(v.x);
        p[4]  = f2tf_f(v.y);
        p[8]  = f2tf_f(v.z);
        p[12] = f2tf_f(v.w);
    }
}

// ---------------- LayerNorm; tf32-rounded + PERMUTED output ----------------
__global__ void ln_kernel(const float* __restrict__ x, const float* __restrict__ g,
                          const float* __restrict__ b, float* __restrict__ out) {
    int row = blockIdx.x;
    int t = threadIdx.x;  // 256 threads, 4 floats each
    const float4* xr = (const float4*)(x + (size_t)row * D_MODEL);
    float4 v = xr[t];
    __shared__ float red[8];

    float s = v.x + v.y + v.z + v.w;
    #pragma unroll
    for (int o = 16; o; o >>= 1) s += __shfl_xor_sync(0xffffffffu, s, o);
    if ((t & 31) == 0) red[t >> 5] = s;
    __syncthreads();
    float tot = red[0]+red[1]+red[2]+red[3]+red[4]+red[5]+red[6]+red[7];
    float mean = tot * (1.0f / D_MODEL);

    float dx = v.x - mean, dy = v.y - mean, dz = v.z - mean, dw = v.w - mean;
    float ss = dx*dx + dy*dy + dz*dz + dw*dw;
    #pragma unroll
    for (int o = 16; o; o >>= 1) ss += __shfl_xor_sync(0xffffffffu, ss, o);
    __syncthreads();
    if ((t & 31) == 0) red[t >> 5] = ss;
    __syncthreads();
    float vtot = red[0]+red[1]+red[2]+red[3]+red[4]+red[5]+red[6]+red[7];
    float inv = 1.0f / (sqrtf(vtot * (1.0f / (D_MODEL - 1))) + 1e-12f);

    float4 g4 = ((const float4*)g)[t];
    float4 b4 = ((const float4*)b)[t];
    float* p = out + (size_t)row * D_MODEL + 16 * (t >> 2) + (t & 3);
    p[0]  = f2tf_f(g4.x * dx * inv + b4.x);
    p[4]  = f2tf_f(g4.y * dy * inv + b4.y);
    p[8]  = f2tf_f(g4.z * dz * inv + b4.z);
    p[12] = f2tf_f(g4.w * dw * inv + b4.w);
}

// ---------------- V transpose: v (permuted) -> vT (permuted) ----------------
__global__ void transpose_v(const float* __restrict__ v, float* __restrict__ vT) {
    __shared__ float tile[32][33];
    int bh = blockIdx.z;             // b*H + h
    int b = bh / N_HEADS, h = bh % N_HEADS;
    int s0 = blockIdx.x * 32;
    int d0 = blockIdx.y * 32;
    int tx = threadIdx.x, ty = threadIdx.y;  // 32 x 8
    const float* src = v + ((size_t)b * SEQ) * D_MODEL + h * D_HEAD;
    int pc = permc(d0 + tx);
    #pragma unroll
    for (int i = 0; i < 32; i += 8)
        tile[ty + i][tx] = src[(size_t)(s0 + ty + i) * D_MODEL + pc];
    __syncthreads();
    float* dst = vT + ((size_t)bh * D_HEAD) * SEQ;
    int ps = permc(s0 + tx);
    #pragma unroll
    for (int i = 0; i < 32; i += 8)
        dst[(size_t)(d0 + ty + i) * SEQ + ps] = tile[tx][ty + i];
}

// ---------------- stat combine: (m_t, l_t) x8 -> per-tile scale exp(m_t-m)/l ------
__global__ void stat_combine(const float* __restrict__ stm, const float* __restrict__ stl,
                             float* __restrict__ scl) {
    int i = blockIdx.x * blockDim.x + threadIdx.x;   // z*1024 + row, 65536 total
    int z = i >> 10, row = i & 1023;
    const float* pm = stm + (size_t)z * 8 * 1024 + row;
    const float* pl = stl + (size_t)z * 8 * 1024 + row;
    float mv[8];
    float m = -1e30f;
    #pragma unroll
    for (int t = 0; t < 8; t++) { mv[t] = pm[t * 1024]; m = fmaxf(m, mv[t]); }
    float ex[8];
    float l = 0.f;
    #pragma unroll
    for (int t = 0; t < 8; t++) { ex[t] = __expf(mv[t] - m); l += pl[t * 1024] * ex[t]; }
    float inv = 1.0f / l;
    float* ps = scl + (size_t)z * 8 * 1024 + row;
    #pragma unroll
    for (int t = 0; t < 8; t++) ps[t * 1024] = ex[t] * inv;
}

// ---------------- tf32 mma.sync GEMM ------------------------------------------------
// MODE 0: cp.async 3-stage pipeline; A and B in PERMUTED gmem layout, pre-rounded
//         tf32; all tile dims divide exactly.
// MODE 2: attn-ctx: A = E (standard layout); p = E * scl; writeback P; 2-buf
//         register staging with in-loop tf32 round. B (vT) permuted -> STS.128.
// PERM_OUT: epilogue writes C in permuted layout (internal tensors feeding GEMMs).
// STATS: scores mode — per-row tile max m_t, C = exp(s - m_t) (standard layout),
//        (m_t, sumexp) -> stm/stl. Requires NT=8, MODE 0.
// Warp grid 4x2, warp tile 32 x (NT*8), CTA tile 128 x (16*NT), BK=16.
template<int MODE, int ROUND_OUT, int STATS, int NT, int PERM_OUT>
__global__ void __launch_bounds__(256, 2)
gemm_mma(const float* __restrict__ A, const float* __restrict__ B,
         float* __restrict__ C, const float* __restrict__ bias, const float* __restrict__ res,
         float* __restrict__ Ck, float* __restrict__ Cv,
         const float* __restrict__ biask, const float* __restrict__ biasv,
         const float* __restrict__ scl, float* __restrict__ stm, float* __restrict__ stl,
         int M, int N, int K, int lda, int ldb, int ldc,
         float scale, int relu, int zmod,
         long long aLo, long long aHi, long long bLo, long long bHi,
         long long cLo, long long cHi)
{
    constexpr int SMW = (MODE == 0) ? 12288 : 8192;   // words
    __shared__ __align__(16) uint32_t sm[SMW];

    int z = blockIdx.z;
    int zlo = z % zmod, zhi = z / zmod;
    A += (size_t)zlo * aLo + (size_t)zhi * aHi;
    B += (size_t)zlo * bLo + (size_t)zhi * bHi;
    size_t coff = (size_t)zlo * cLo + (size_t)zhi * cHi;
    C += coff;
    if (res) res += coff;

    const int tid = threadIdx.x, lane = tid & 31, warp = tid >> 5;
    const int wm = (warp & 3) * 32, wn = (warp >> 2) * (NT * 8);
    const int m0 = blockIdx.y * 128, n0 = blockIdx.x * (16 * NT);

    // compute-side fragment bases (chunk layout identical in both modes)
    const int ft = lane & 3, frl = lane >> 2;
    const int fu = ft ^ ((frl >> 1) & 3);
    const uint32_t ldAw = (uint32_t)((wm + frl) * 16 + 4 * fu);
    const uint32_t ldBw = (uint32_t)(2048 + (wn + frl) * 16 + 4 * fu);

    float acc[2][NT][4];
    #pragma unroll
    for (int i = 0; i < 2; i++)
        #pragma unroll
        for (int j = 0; j < NT; j++)
            #pragma unroll
            for (int c = 0; c < 4; c++) acc[i][j][c] = 0.f;

    const int nk = K / 16;

    auto compute_at = [&](const uint32_t* base) {
        uint4 af[2][2];
        #pragma unroll
        for (int mt = 0; mt < 2; mt++)
            #pragma unroll
            for (int h = 0; h < 2; h++)
                af[mt][h] = *(const uint4*)&base[ldAw + mt * 256 + h * 128];
        #pragma unroll
        for (int nt = 0; nt < NT; nt++) {
            uint4 bf = *(const uint4*)&base[ldBw + nt * 128];
            #pragma unroll
            for (int mt = 0; mt < 2; mt++) {
                mma_tf32(acc[mt][nt], af[mt][0].x, af[mt][1].x, af[mt][0].y, af[mt][1].y,
                         bf.x, bf.y);
                mma_tf32(acc[mt][nt], af[mt][0].z, af[mt][1].z, af[mt][0].w, af[mt][1].w,
                         bf.z, bf.w);
            }
        }
    };

    if (MODE == 0) {
        // ---- cp.async 3-stage pipeline ----
        const uint32_t smem_base = smem_u32(sm);
        // per-thread unit assignments: id = tid + 256*j -> row id>>2, unit id&3
        uint32_t saw[2], sbw[2];
        const float *ga[2], *gb[2];
        #pragma unroll
        for (int j = 0; j < 2; j++) {
            int id = tid + 256 * j;
            int r = id >> 2, u = id & 3;
            int up = u ^ ((r >> 1) & 3);
            saw[j] = (uint32_t)((r * 16 + 4 * up) * 4);
            sbw[j] = (uint32_t)((2048 + r * 16 + 4 * up) * 4);
            ga[j] = A + (size_t)(m0 + r) * lda + 4 * u;
            gb[j] = B + (size_t)(n0 + r) * ldb + 4 * u;
        }
        auto issue = [&](int tile, int stg) {
            const int k0 = tile * 16;
            const uint32_t sb = smem_base + (uint32_t)stg * 16384u;
            #pragma unroll
            for (int j = 0; j < 2; j++) cp_async16(sb + saw[j], ga[j] + k0);
            #pragma unroll
            for (int j = 0; j < 2; j++) cp_async16(sb + sbw[j], gb[j] + k0);
            cp_commit();
        };
        issue(0, 0);
        issue(1, 1);
        int st = 0;
        for (int t = 0; t < nk; ++t) {
            cp_wait1();
            __syncthreads();
            compute_at(sm + st * 4096);
            if (t + 2 < nk) {
                int st2 = st + 2; if (st2 >= 3) st2 -= 3;
                issue(t + 2, st2);
            } else {
                cp_commit();
            }
            if (++st == 3) st = 0;
        }
        __syncthreads();
    } else {
        // ---- MODE 2: ctx. A standard E + transform + writeback; B permuted. ----
        const int lr = tid >> 2, c4 = tid & 3, sw = (lr >> 1) & 3;
        uint32_t stA[4];
        #pragma unroll
        for (int j = 0; j < 4; j++) stA[j] = lr * 16 + 4 * (j ^ sw) + c4;
        uint32_t stB = 2048 + lr * 16 + 4 * (c4 ^ sw);
        float* PW = (float*)A;
        float4 aR[2]; uint4 bRr;
        uint32_t ldA2 = ldAw, ldB2 = ldBw;

        auto loadg = [&](int t) {
            int k0 = t * 16 + c4 * 4;
            const float* sp = scl + ((size_t)z * 8 + (t >> 3)) * 1024 + m0 + lr;
            float s0 = sp[0], s1 = sp[64];
            #pragma unroll
            for (int i = 0; i < 2; i++) {
                int gm = m0 + lr + i * 64;
                aR[i] = *(const float4*)(A + (size_t)gm * lda + k0);
                float s = i ? s1 : s0;
                aR[i].x *= s; aR[i].y *= s; aR[i].z *= s; aR[i].w *= s;
                *(float4*)(PW + (size_t)gm * lda + k0) = aR[i];
            }
            bRr = *(const uint4*)(B + (size_t)(n0 + lr) * ldb + k0);
        };
        auto stores = [&]() {
            #pragma unroll
            for (int i = 0; i < 2; i++) {
                float av[4] = {aR[i].x, aR[i].y, aR[i].z, aR[i].w};
                #pragma unroll
                for (int j = 0; j < 4; j++)
                    sm[stA[j] + i * 1024] = f2tf(av[j]);
            }
            *(uint4*)&sm[stB] = bRr;
            #pragma unroll
            for (int j = 0; j < 4; j++) stA[j] ^= 4096;
            stB ^= 4096;
        };
        loadg(0); stores(); __syncthreads();
        for (int t = 0; t < nk; ++t) {
            if (t + 1 < nk) loadg(t + 1);
            compute_at(sm + ((t & 1) ? 4096 : 0));
            if (t + 1 < nk) stores();
            __syncthreads();
        }
    }

    if (STATS) {
        // ---- scores mode: per-row tile max, write E = exp(s - m_t), store stats ----
        float* smf = (float*)sm;
        const int g = warp >> 2;
        const int rl = lane >> 2;
        float lmax[2][2];
        #pragma unroll
        for (int mt = 0; mt < 2; mt++)
            #pragma unroll
            for (int h = 0; h < 2; h++) {
                float v = -1e30f;
                #pragma unroll
                for (int nt = 0; nt < NT; nt++) {
                    v = fmaxf(v, acc[mt][nt][2 * h]);
                    v = fmaxf(v, acc[mt][nt][2 * h + 1]);
                }
                lmax[mt][h] = v * scale;
            }
        #pragma unroll
        for (int o = 1; o < 4; o <<= 1)
            #pragma unroll
            for (int mt = 0; mt < 2; mt++)
                #pragma unroll
                for (int h = 0; h < 2; h++)
                    lmax[mt][h] = fmaxf(lmax[mt][h], __shfl_xor_sync(0xffffffffu, lmax[mt][h], o));
        __syncthreads();
        if ((lane & 3) == 0)
            #pragma unroll
            for (int mt = 0; mt < 2; mt++)
                #pragma unroll
                for (int h = 0; h < 2; h++)
                    smf[g * 128 + wm + mt * 16 + h * 8 + rl] = lmax[mt][h];
        __syncthreads();
        float rmax[2][2], lsum[2][2];
        #pragma unroll
        for (int mt = 0; mt < 2; mt++)
            #pragma unroll
            for (int h = 0; h < 2; h++) {
                int row = wm + mt * 16 + h * 8 + rl;
                rmax[mt][h] = fmaxf(smf[row], smf[128 + row]);
                lsum[mt][h] = 0.f;
            }
        #pragma unroll
        for (int mt = 0; mt < 2; ++mt) {
            #pragma unroll
            for (int nt = 0; nt < NT; ++nt) {
                int rbase = m0 + wm + mt * 16 + rl;
                int cbase = n0 + wn + nt * 8 + (lane & 3) * 2;
                #pragma unroll
                for (int h = 0; h < 2; ++h) {
                    float e0 = __expf(acc[mt][nt][2 * h]     * scale - rmax[mt][h]);
                    float e1 = __expf(acc[mt][nt][2 * h + 1] * scale - rmax[mt][h]);
                    *(float2*)(C + (size_t)(rbase + h * 8) * ldc + cbase) = make_float2(e0, e1);
                    lsum[mt][h] += e0 + e1;
                }
            }
        }
        #pragma unroll
        for (int o = 1; o < 4; o <<= 1)
            #pragma unroll
            for (int mt = 0; mt < 2; mt++)
                #pragma unroll
                for (int h = 0; h < 2; h++)
                    lsum[mt][h] += __shfl_xor_sync(0xffffffffu, lsum[mt][h], o);
        if ((lane & 3) == 0)
            #pragma unroll
            for (int mt = 0; mt < 2; mt++)
                #pragma unroll
                for (int h = 0; h < 2; h++)
                    smf[256 + g * 128 + wm + mt * 16 + h * 8 + rl] = lsum[mt][h];
        __syncthreads();
        if (g == 0 && (lane & 3) == 0) {
            #pragma unroll
            for (int mt = 0; mt < 2; mt++)
                #pragma unroll
                for (int h = 0; h < 2; h++) {
                    int row = wm + mt * 16 + h * 8 + rl;
                    size_t idx = ((size_t)z * 8 + blockIdx.x) * 1024 + m0 + row;
                    stm[idx] = rmax[mt][h];
                    stl[idx] = smf[256 + row] + smf[384 + row];
                }
        }
    } else {
        // ---- normal epilogue (QKV 3-way select; optional permuted C) ----
        float* Cp = C; const float* bp = bias; int noff = 0;
        if (Ck) {
            if (n0 >= 2048)      { Cp = Cv; bp = biasv; noff = 2048; }
            else if (n0 >= 1024) { Cp = Ck; bp = biask; noff = 1024; }
        }
        #pragma unroll
        for (int mt = 0; mt < 2; ++mt) {
            #pragma unroll
            for (int nt = 0; nt < NT; ++nt) {
                int rbase = m0 + wm + mt * 16 + (lane >> 2);
                int cbase = n0 + wn + nt * 8 + (lane & 3) * 2;
                #pragma unroll
                for (int h = 0; h < 2; ++h) {
                    int rr = rbase + h * 8;
                    int cl = cbase - noff;
                    float v0 = acc[mt][nt][h * 2 + 0] * scale;
                    float v1 = acc[mt][nt][h * 2 + 1] * scale;
                    if (bp)  { float2 bb = *(const float2*)(bp + cl); v0 += bb.x; v1 += bb.y; }
                    if (res) { float2 r2 = *(const float2*)(res + (size_t)rr * ldc + cl); v0 += r2.x; v1 += r2.y; }
                    if (relu) { v0 = fmaxf(v0, 0.f); v1 = fmaxf(v1, 0.f); }
                    if (ROUND_OUT) { v0 = f2tf_f(v0); v1 = f2tf_f(v1); }
                    if (PERM_OUT) {
                        int p = permc(cl);               // cl even -> pair at p, p+4
                        float* rp = Cp + (size_t)rr * ldc;
                        rp[p] = v0; rp[p + 4] = v1;
                    } else {
                        *(float2*)(Cp + (size_t)rr * ldc + cl) = make_float2(v0, v1);
                    }
                }
            }
        }
    }
}

// ---------------- launch ----------------
extern "C" void kernel_launch(void* const* d_in, const int* in_sizes, int n_in,
                              void* d_out, int out_size) {
    const float* x     = (const float*)d_in[0];
    const float* ln1_g = (const float*)d_in[1];
    const float* ln1_b = (const float*)d_in[2];
    const float* wq    = (const float*)d_in[3];
    const float* bq    = (const float*)d_in[4];
    const float* wk    = (const float*)d_in[5];
    const float* bk    = (const float*)d_in[6];
    const float* wv    = (const float*)d_in[7];
    const float* bv    = (const float*)d_in[8];
    const float* ln2_g = (const float*)d_in[9];
    const float* ln2_b = (const float*)d_in[10];
    const float* w1    = (const float*)d_in[11];
    const float* b1    = (const float*)d_in[12];
    const float* w2    = (const float*)d_in[13];
    const float* b2    = (const float*)d_in[14];

    float* out  = (float*)d_out;
    float* attn = out + (size_t)BATCH * SEQ * D_MODEL;

    float *h, *q, *k, *v, *vT, *o1, *h2, *ff, *wqkv, *w1r, *w2r, *stm, *stl, *scl;
    cudaGetSymbolAddress((void**)&h,    g_h);
    cudaGetSymbolAddress((void**)&q,    g_q);
    cudaGetSymbolAddress((void**)&k,    g_k);
    cudaGetSymbolAddress((void**)&v,    g_v);
    cudaGetSymbolAddress((void**)&vT,   g_vT);
    cudaGetSymbolAddress((void**)&o1,   g_o1);
    cudaGetSymbolAddress((void**)&h2,   g_h2);
    cudaGetSymbolAddress((void**)&ff,   g_ff);
    cudaGetSymbolAddress((void**)&wqkv, g_wqkv);
    cudaGetSymbolAddress((void**)&w1r,  g_w1r);
    cudaGetSymbolAddress((void**)&w2r,  g_w2r);
    cudaGetSymbolAddress((void**)&stm,  g_stm);
    cudaGetSymbolAddress((void**)&stl,  g_stl);
    cudaGetSymbolAddress((void**)&scl,  g_scl);

    dim3 blk(256);
    const int N4_1M = D_MODEL * D_MODEL / 4;      // 262144
    const int N4_4M = D_FF * D_MODEL / 4;         // 1048576

    // 0) pre-round weights into scratch (permuted tf32 layout)
    round_copy<<<(N4_1M + 255) / 256, 256>>>((const float4*)wq, wqkv, N4_1M);
    round_copy<<<(N4_1M + 255) / 256, 256>>>((const float4*)wk, wqkv + D_MODEL * D_MODEL, N4_1M);
    round_copy<<<(N4_1M + 255) / 256, 256>>>((const float4*)wv, wqkv + 2 * D_MODEL * D_MODEL, N4_1M);
    round_copy<<<(N4_4M + 255) / 256, 256>>>((const float4*)w1, w1r, N4_4M);
    round_copy<<<(N4_4M + 255) / 256, 256>>>((const float4*)w2, w2r, N4_4M);

    // 1) LN1 (rounded, permuted output)
    ln_kernel<<<M_TOK, 256>>>(x, ln1_g, ln1_b, h);

    // 2) fused QKV: [4096,3072] = h @ wqkv^T; q/k/v rounded + permuted
    gemm_mma<0, 1, 0, 8, 1><<<dim3(24, 32, 1), blk>>>(h, wqkv, q, bq, nullptr, k, v, bk, bv,
        nullptr, nullptr, nullptr,
        M_TOK, 3 * D_MODEL, D_MODEL, D_MODEL, D_MODEL, D_MODEL, 1.f, 0, 1, 0,0,0,0,0,0);

    // 3) V transpose (permuted in -> permuted out)
    transpose_v<<<dim3(32, 2, BATCH * N_HEADS), dim3(32, 8)>>>(v, vT);

    // 4) scores -> E = exp(s/8 - m_tile) into attn region (standard layout) + stats
    gemm_mma<0, 0, 1, 8, 0><<<dim3(8, 8, N_HEADS * BATCH), blk>>>(q, k, attn, nullptr, nullptr,
        nullptr, nullptr, nullptr, nullptr,
        nullptr, stm, stl,
        SEQ, SEQ, D_HEAD, D_MODEL, D_MODEL, SEQ, 0.125f, 0, BATCH,
        (long long)SEQ * D_MODEL, 64,
        (long long)SEQ * D_MODEL, 64,
        (long long)SEQ * SEQ, (long long)BATCH * SEQ * SEQ);

    // 5) combine per-tile stats -> per-(tile,row) scale exp(m_t-m)/l
    stat_combine<<<256, 256>>>(stm, stl, scl);

    // 6) ctx = P @ vT^T (+ residual x); rescale E->P, write P back (standard)
    gemm_mma<2, 0, 0, 4, 0><<<dim3(1, 8, N_HEADS * BATCH), blk>>>(attn, vT, o1, nullptr, x,
        nullptr, nullptr, nullptr, nullptr,
        scl, nullptr, nullptr,
        SEQ, D_HEAD, SEQ, SEQ, SEQ, D_MODEL, 1.f, 0, BATCH,
        (long long)SEQ * SEQ, (long long)BATCH * SEQ * SEQ,
        (long long)N_HEADS * D_HEAD * SEQ, (long long)D_HEAD * SEQ,
        (long long)SEQ * D_MODEL, 64);

    // 7) LN2 (rounded, permuted output)
    ln_kernel<<<M_TOK, 256>>>(o1, ln2_g, ln2_b, h2);

    // 8) FFN1: relu(h2 @ w1^T + b1), rounded + permuted output
    gemm_mma<0, 1, 0, 8, 1><<<dim3(32, 32, 1), blk>>>(h2, w1r, ff, b1, nullptr,
        nullptr, nullptr, nullptr, nullptr,
        nullptr, nullptr, nullptr,
        M_TOK, D_FF, D_MODEL, D_MODEL, D_MODEL, D_FF, 1.f, 1, 1, 0,0,0,0,0,0);

    // 9) FFN2: ff @ w2^T + b2 + o1 -> final out (standard layout)
    gemm_mma<0, 0, 0, 8, 0><<<dim3(8, 32, 1), blk>>>(ff, w2r, out, b2, o1,
        nullptr, nullptr, nullptr, nullptr,
        nullptr, nullptr, nullptr,
        M_TOK, D_MODEL, D_FF, D_FF, D_FF, D_MODEL, 1.f, 0, 1, 0,0,0,0,0,0);
}